// round 1
// baseline (speedup 1.0000x reference)
#include <cuda_runtime.h>
#include <math.h>

#define S_LEN 2048
#define DM    2048
#define NH    16
#define NKV   4
#define HD    128

// ---------------- scratch (device globals; no runtime allocation) ----------------
__device__ float g_qlin[4096u * 2048u];   // x @ Wq   [B*S, 2048]
__device__ float g_klin[4096u * 512u];    // x @ Wk   [B*S, 512]
__device__ float g_vlin[4096u * 512u];    // x @ Wv   [B*S, 512]
__device__ float g_q[4096u * 2048u];      // roped Q  [B, NH, S, HD]
__device__ float g_k[2u * 4u * 2048u * 128u]; // roped K [B, NKV, S, HD]
__device__ float g_v[2u * 4u * 2048u * 128u]; // V       [B, NKV, S, HD]
__device__ float g_att[4096u * 2048u];    // attention output [B*S, NH*HD]

// ---------------- SGEMM: C[M,N] = A[M,K] * B[K,N], all row-major, fp32 ----------------
// BM=BN=128, BK=16, 256 threads, 8x8 micro-tile per thread.
__global__ __launch_bounds__(256) void sgemm128(int M, int N, int K,
    const float* __restrict__ A, const float* __restrict__ B, float* __restrict__ C) {
    __shared__ float As[16][128];   // transposed: As[k][m]
    __shared__ float Bs[16][128];   // Bs[k][n]

    const int tid = threadIdx.x;
    const int bx = blockIdx.x;      // N tile
    const int by = blockIdx.y;      // M tile

    A += (size_t)by * 128 * K;
    B += (size_t)bx * 128;
    C += (size_t)by * 128 * N + (size_t)bx * 128;

    const int trow = tid >> 4;      // 0..15
    const int tcol = tid & 15;      // 0..15

    float acc[8][8];
#pragma unroll
    for (int i = 0; i < 8; i++)
#pragma unroll
        for (int j = 0; j < 8; j++) acc[i][j] = 0.f;

    const int arow = tid >> 2;           // 0..63
    const int acol = (tid & 3) << 2;     // 0,4,8,12
    const int brow = tid >> 5;           // 0..7
    const int bcol = (tid & 31) << 2;    // 0..124

    for (int k0 = 0; k0 < K; k0 += 16) {
#pragma unroll
        for (int i = 0; i < 2; i++) {
            const float4 va = *(const float4*)(A + (size_t)(arow + i * 64) * K + k0 + acol);
            As[acol + 0][arow + i * 64] = va.x;
            As[acol + 1][arow + i * 64] = va.y;
            As[acol + 2][arow + i * 64] = va.z;
            As[acol + 3][arow + i * 64] = va.w;
            const float4 vb = *(const float4*)(B + (size_t)(k0 + brow + i * 8) * N + bcol);
            *(float4*)&Bs[brow + i * 8][bcol] = vb;
        }
        __syncthreads();
#pragma unroll
        for (int kk = 0; kk < 16; kk++) {
            float ar[8], br[8];
#pragma unroll
            for (int i = 0; i < 8; i++) ar[i] = As[kk][trow * 8 + i];
#pragma unroll
            for (int j = 0; j < 8; j++) br[j] = Bs[kk][tcol * 8 + j];
#pragma unroll
            for (int i = 0; i < 8; i++)
#pragma unroll
                for (int j = 0; j < 8; j++) acc[i][j] += ar[i] * br[j];
        }
        __syncthreads();
    }

#pragma unroll
    for (int i = 0; i < 8; i++)
#pragma unroll
        for (int j = 0; j < 8; j += 4) {
            float4 v = make_float4(acc[i][j], acc[i][j + 1], acc[i][j + 2], acc[i][j + 3]);
            *(float4*)(C + (size_t)(trow * 8 + i) * N + tcol * 8 + j) = v;
        }
}

// ---------------- RoPE + [B,S,h*HD] -> [B,h,S,HD] relayout ----------------
// One thread per (b,h,s,pair). Total threads = B*nh*S*64.
__global__ void rope_kernel(const float* __restrict__ lin, const float* __restrict__ cosv,
                            const float* __restrict__ sinv, float* __restrict__ out, int nh) {
    int idx = blockIdx.x * blockDim.x + threadIdx.x;
    int i = idx & 63;
    int s = (idx >> 6) & (S_LEN - 1);
    int bh = idx >> 17;              // b*nh + h
    int h = bh % nh;
    int b = bh / nh;

    float c  = cosv[s * 64 + i];
    float sn = sinv[s * 64 + i];
    const float* src = lin + ((size_t)(b * S_LEN + s)) * (nh * HD) + h * HD + 2 * i;
    float e = src[0], o = src[1];
    float* dst = out + (((size_t)bh) * S_LEN + s) * HD + 2 * i;
    dst[0] = e * c - o * sn;
    dst[1] = e * sn + o * c;
}

// ---------------- V relayout [B,S,kv*HD] -> [B,kv,S,HD] ----------------
__global__ void vtrans_kernel(const float* __restrict__ lin, float* __restrict__ out) {
    int idx = blockIdx.x * blockDim.x + threadIdx.x;   // over 2*4*2048*128
    int d = idx & 127;
    int s = (idx >> 7) & (S_LEN - 1);
    int kvb = idx >> 18;             // b*NKV + kv
    int kv = kvb & 3;
    int b = kvb >> 2;
    out[idx] = lin[((size_t)(b * S_LEN + s)) * (NKV * HD) + kv * HD + d];
}

// ---------------- Flash attention (fp32, causal, GQA) ----------------
// Block = (q-tile 64, head, batch). 256 threads: tr=tid/16 (4 q rows), tc=tid%16.
// Column mapping for k and d dims: c = tc + 16*j  (conflict-free smem reads).
struct AttSmem {
    float Qt[128][65];   // Qt[d][q], padded
    float Kt[128][65];   // Kt[d][k], padded
    float Vs[64][128];   // Vs[k][d]
    float Sc[64][64];    // scores / probabilities
    float row_m[64];
    float row_l[64];
    float row_alpha[64];
};

__global__ __launch_bounds__(256) void attn_kernel(const float* __restrict__ Q,
    const float* __restrict__ K, const float* __restrict__ V, float* __restrict__ Out) {
    extern __shared__ char smem_raw[];
    AttSmem& sm = *reinterpret_cast<AttSmem*>(smem_raw);

    const int qt = blockIdx.x;      // 0..31
    const int h  = blockIdx.y;      // 0..15
    const int b  = blockIdx.z;      // 0..1
    const int kvh = h >> 2;         // N_REP = 4
    const int tid = threadIdx.x;
    const int tr = tid >> 4, tc = tid & 15;
    const float scale = 0.08838834764831845f;   // 1/sqrt(128)

    const float* Qg = Q + (((size_t)(b * NH + h)) * S_LEN + qt * 64) * HD;
    const float* Kg = K + ((size_t)(b * NKV + kvh)) * S_LEN * HD;
    const float* Vg = V + ((size_t)(b * NKV + kvh)) * S_LEN * HD;

    // load Q tile transposed
#pragma unroll
    for (int it = 0; it < 32; it++) {
        int i = tid + it * 256;
        int q = i >> 7, d = i & 127;
        sm.Qt[d][q] = Qg[i];
    }
    if (tid < 64) { sm.row_m[tid] = -1e30f; sm.row_l[tid] = 0.f; }

    float o[4][8];
#pragma unroll
    for (int i = 0; i < 4; i++)
#pragma unroll
        for (int j = 0; j < 8; j++) o[i][j] = 0.f;

    __syncthreads();

    for (int kt = 0; kt <= qt; kt++) {
        const float* Ktg = Kg + (size_t)kt * 64 * HD;
        const float* Vtg = Vg + (size_t)kt * 64 * HD;
#pragma unroll
        for (int it = 0; it < 32; it++) {
            int i = tid + it * 256;
            int k = i >> 7, d = i & 127;
            sm.Kt[d][k] = Ktg[i];
            sm.Vs[k][d] = Vtg[i];
        }
        __syncthreads();

        // S = Q K^T
        float acc[4][4];
#pragma unroll
        for (int i = 0; i < 4; i++)
#pragma unroll
            for (int j = 0; j < 4; j++) acc[i][j] = 0.f;

        for (int d = 0; d < 128; d++) {
            float qv[4], kv[4];
#pragma unroll
            for (int i = 0; i < 4; i++) qv[i] = sm.Qt[d][tr * 4 + i];
#pragma unroll
            for (int j = 0; j < 4; j++) kv[j] = sm.Kt[d][tc + 16 * j];
#pragma unroll
            for (int i = 0; i < 4; i++)
#pragma unroll
                for (int j = 0; j < 4; j++) acc[i][j] += qv[i] * kv[j];
        }

        const bool diag = (kt == qt);
#pragma unroll
        for (int i = 0; i < 4; i++) {
            int q = tr * 4 + i;
#pragma unroll
            for (int j = 0; j < 4; j++) {
                int k = tc + 16 * j;
                float sv = acc[i][j] * scale;
                if (diag && k > q) sv = -1e30f;
                sm.Sc[q][k] = sv;
            }
        }
        __syncthreads();

        // online softmax: 4 threads per row
        {
            const int r = tid >> 2, part = tid & 3;
            float m_old = sm.row_m[r];
            float mx = m_old;
#pragma unroll
            for (int k = 0; k < 16; k++) mx = fmaxf(mx, sm.Sc[r][part * 16 + k]);
            mx = fmaxf(mx, __shfl_xor_sync(0xffffffffu, mx, 1));
            mx = fmaxf(mx, __shfl_xor_sync(0xffffffffu, mx, 2));
            float sum = 0.f;
#pragma unroll
            for (int k = 0; k < 16; k++) {
                float p = __expf(sm.Sc[r][part * 16 + k] - mx);
                sm.Sc[r][part * 16 + k] = p;
                sum += p;
            }
            sum += __shfl_xor_sync(0xffffffffu, sum, 1);
            sum += __shfl_xor_sync(0xffffffffu, sum, 2);
            if (part == 0) {
                float alpha = __expf(m_old - mx);
                sm.row_alpha[r] = alpha;
                sm.row_l[r] = alpha * sm.row_l[r] + sum;
                sm.row_m[r] = mx;
            }
        }
        __syncthreads();

        // rescale O and accumulate P*V
        float al[4];
#pragma unroll
        for (int i = 0; i < 4; i++) al[i] = sm.row_alpha[tr * 4 + i];
#pragma unroll
        for (int i = 0; i < 4; i++)
#pragma unroll
            for (int j = 0; j < 8; j++) o[i][j] *= al[i];

        for (int k = 0; k < 64; k++) {
            float pv[4], vv[8];
#pragma unroll
            for (int i = 0; i < 4; i++) pv[i] = sm.Sc[tr * 4 + i][k];
#pragma unroll
            for (int j = 0; j < 8; j++) vv[j] = sm.Vs[k][tc + 16 * j];
#pragma unroll
            for (int i = 0; i < 4; i++)
#pragma unroll
                for (int j = 0; j < 8; j++) o[i][j] += pv[i] * vv[j];
        }
        __syncthreads();   // protect Kt/Vs/Sc before next tile load
    }

    // write: Out[(b*S + q_global)*DM + h*HD + d], d = tc + 16*j
#pragma unroll
    for (int i = 0; i < 4; i++) {
        int q = tr * 4 + i;
        float inv = 1.f / sm.row_l[q];
        size_t rowoff = ((size_t)(b * S_LEN) + qt * 64 + q) * DM + h * HD;
#pragma unroll
        for (int j = 0; j < 8; j++)
            Out[rowoff + tc + 16 * j] = o[i][j] * inv;
    }
}

// ---------------- launch ----------------
extern "C" void kernel_launch(void* const* d_in, const int* in_sizes, int n_in,
                              void* d_out, int out_size) {
    const float* x  = (const float*)d_in[0];
    const float* rc = (const float*)d_in[1];
    const float* rs = (const float*)d_in[2];
    const float* Wq = (const float*)d_in[3];
    const float* Wk = (const float*)d_in[4];
    const float* Wv = (const float*)d_in[5];
    const float* Wo = (const float*)d_in[6];
    float* out = (float*)d_out;

    float *qlin, *klin, *vlin, *q, *k, *v, *att;
    cudaGetSymbolAddress((void**)&qlin, g_qlin);
    cudaGetSymbolAddress((void**)&klin, g_klin);
    cudaGetSymbolAddress((void**)&vlin, g_vlin);
    cudaGetSymbolAddress((void**)&q,    g_q);
    cudaGetSymbolAddress((void**)&k,    g_k);
    cudaGetSymbolAddress((void**)&v,    g_v);
    cudaGetSymbolAddress((void**)&att,  g_att);

    cudaFuncSetAttribute(attn_kernel, cudaFuncAttributeMaxDynamicSharedMemorySize,
                         (int)sizeof(AttSmem));

    const int M = 2 * S_LEN;  // 4096

    // projections
    sgemm128<<<dim3(2048 / 128, M / 128), 256>>>(M, 2048, 2048, x, Wq, qlin);
    sgemm128<<<dim3(512 / 128,  M / 128), 256>>>(M, 512,  2048, x, Wk, klin);
    sgemm128<<<dim3(512 / 128,  M / 128), 256>>>(M, 512,  2048, x, Wv, vlin);

    // rope + relayout
    rope_kernel<<<(2 * NH  * S_LEN * 64) / 256, 256>>>(qlin, rc, rs, q, NH);
    rope_kernel<<<(2 * NKV * S_LEN * 64) / 256, 256>>>(klin, rc, rs, k, NKV);
    vtrans_kernel<<<(2 * NKV * S_LEN * 128) / 256, 256>>>(vlin, v);

    // attention
    attn_kernel<<<dim3(S_LEN / 64, NH, 2), 256, sizeof(AttSmem)>>>(q, k, v, att);

    // output projection
    sgemm128<<<dim3(2048 / 128, M / 128), 256>>>(M, 2048, 2048, att, Wo, out);
}

// round 6
// speedup vs baseline: 3.0136x; 3.0136x over previous
#include <cuda_runtime.h>
#include <cstdint>
#include <math.h>

#define S_LEN 2048
#define DM    2048
#define NH    16
#define NKV   4
#define HD    128

// ---------------- scratch (device globals; no runtime allocation) ----------------
__device__ float g_qlin[4096u * 2048u];   // x @ Wq   [B*S, 2048]
__device__ float g_klin[4096u * 512u];    // x @ Wk   [B*S, 512]
__device__ float g_vlin[4096u * 512u];    // x @ Wv   [B*S, 512]
__device__ float g_q[4096u * 2048u];      // roped Q  [B, NH, S, HD]
__device__ float g_k[2u * 4u * 2048u * 128u]; // roped K [B, NKV, S, HD]
__device__ float g_v[2u * 4u * 2048u * 128u]; // V       [B, NKV, S, HD]
__device__ float g_att[4096u * 2048u];    // attention output [B*S, NH*HD]

// ---------------- helpers ----------------
__device__ __forceinline__ uint32_t f2tf32(float x) {
    uint32_t r;
    asm("cvt.rna.tf32.f32 %0, %1;" : "=r"(r) : "f"(x));
    return r;
}
__device__ __forceinline__ float f2tf32f(float x) { return __uint_as_float(f2tf32(x)); }

__device__ __forceinline__ void mma_tf32(float c[4], uint32_t a0, uint32_t a1,
                                         uint32_t a2, uint32_t a3,
                                         uint32_t b0, uint32_t b1) {
    asm volatile(
        "mma.sync.aligned.m16n8k8.row.col.f32.tf32.tf32.f32 "
        "{%0,%1,%2,%3}, {%4,%5,%6,%7}, {%8,%9}, {%0,%1,%2,%3};\n"
        : "+f"(c[0]), "+f"(c[1]), "+f"(c[2]), "+f"(c[3])
        : "r"(a0), "r"(a1), "r"(a2), "r"(a3), "r"(b0), "r"(b1));
}

// ---------------- TF32 GEMM: C[M,N] = A[M,K] * B[K,N], row-major ----------------
// Block tile 128x128, BK=32, 256 threads (8 warps), warp tile 64x32.
__global__ __launch_bounds__(256) void tf32_gemm(int M, int N, int K,
    const float* __restrict__ A, const float* __restrict__ B, float* __restrict__ C) {
    __shared__ float As[128][36];    // [m][k], stride 36 -> bank 4g+t, conflict-free
    __shared__ float Bs[32][136];    // [k][n], stride 136 -> bank 8t+g, conflict-free

    const int tid  = threadIdx.x;
    const int lane = tid & 31;
    const int wid  = tid >> 5;
    const int g = lane >> 2;
    const int t = lane & 3;
    const int wm = (wid >> 2) * 64;
    const int wn = (wid & 3) * 32;

    A += (size_t)blockIdx.y * 128 * K;
    B += (size_t)blockIdx.x * 128;
    C += (size_t)blockIdx.y * 128 * N + (size_t)blockIdx.x * 128;

    float acc[4][4][4];
#pragma unroll
    for (int mi = 0; mi < 4; mi++)
#pragma unroll
        for (int ni = 0; ni < 4; ni++)
#pragma unroll
            for (int r = 0; r < 4; r++) acc[mi][ni][r] = 0.f;

    for (int k0 = 0; k0 < K; k0 += 32) {
#pragma unroll
        for (int it = 0; it < 4; it++) {
            int idx = tid + it * 256;
            int r = idx >> 3, c4 = (idx & 7) << 2;
            float4 v = *(const float4*)(A + (size_t)r * K + k0 + c4);
            As[r][c4 + 0] = f2tf32f(v.x);
            As[r][c4 + 1] = f2tf32f(v.y);
            As[r][c4 + 2] = f2tf32f(v.z);
            As[r][c4 + 3] = f2tf32f(v.w);
        }
#pragma unroll
        for (int it = 0; it < 4; it++) {
            int idx = tid + it * 256;
            int r = idx >> 5, c4 = (idx & 31) << 2;
            float4 v = *(const float4*)(B + (size_t)(k0 + r) * N + c4);
            Bs[r][c4 + 0] = f2tf32f(v.x);
            Bs[r][c4 + 1] = f2tf32f(v.y);
            Bs[r][c4 + 2] = f2tf32f(v.z);
            Bs[r][c4 + 3] = f2tf32f(v.w);
        }
        __syncthreads();

#pragma unroll
        for (int kk = 0; kk < 32; kk += 8) {
            uint32_t af[4][4], bf[4][2];
#pragma unroll
            for (int mi = 0; mi < 4; mi++) {
                int r0 = wm + mi * 16 + g;
                af[mi][0] = __float_as_uint(As[r0][kk + t]);
                af[mi][1] = __float_as_uint(As[r0 + 8][kk + t]);
                af[mi][2] = __float_as_uint(As[r0][kk + t + 4]);
                af[mi][3] = __float_as_uint(As[r0 + 8][kk + t + 4]);
            }
#pragma unroll
            for (int ni = 0; ni < 4; ni++) {
                int c0 = wn + ni * 8 + g;
                bf[ni][0] = __float_as_uint(Bs[kk + t][c0]);
                bf[ni][1] = __float_as_uint(Bs[kk + t + 4][c0]);
            }
#pragma unroll
            for (int mi = 0; mi < 4; mi++)
#pragma unroll
                for (int ni = 0; ni < 4; ni++)
                    mma_tf32(acc[mi][ni], af[mi][0], af[mi][1], af[mi][2], af[mi][3],
                             bf[ni][0], bf[ni][1]);
        }
        __syncthreads();
    }

#pragma unroll
    for (int mi = 0; mi < 4; mi++) {
#pragma unroll
        for (int ni = 0; ni < 4; ni++) {
            int row = wm + mi * 16 + g;
            int col = wn + ni * 8 + 2 * t;
            *(float2*)(C + (size_t)row * N + col) =
                make_float2(acc[mi][ni][0], acc[mi][ni][1]);
            *(float2*)(C + (size_t)(row + 8) * N + col) =
                make_float2(acc[mi][ni][2], acc[mi][ni][3]);
        }
    }
}

// ---------------- RoPE + [B,S,h*HD] -> [B,h,S,HD] relayout ----------------
__global__ void rope_kernel(const float* __restrict__ lin, const float* __restrict__ cosv,
                            const float* __restrict__ sinv, float* __restrict__ out, int nh) {
    int idx = blockIdx.x * blockDim.x + threadIdx.x;
    int i = idx & 63;
    int s = (idx >> 6) & (S_LEN - 1);
    int bh = idx >> 17;
    int h = bh % nh;
    int b = bh / nh;

    float c  = cosv[s * 64 + i];
    float sn = sinv[s * 64 + i];
    const float* src = lin + ((size_t)(b * S_LEN + s)) * (nh * HD) + h * HD + 2 * i;
    float e = src[0], o = src[1];
    float* dst = out + (((size_t)bh) * S_LEN + s) * HD + 2 * i;
    dst[0] = e * c - o * sn;
    dst[1] = e * sn + o * c;
}

// ---------------- V relayout [B,S,kv*HD] -> [B,kv,S,HD] ----------------
__global__ void vtrans_kernel(const float* __restrict__ lin, float* __restrict__ out) {
    int idx = blockIdx.x * blockDim.x + threadIdx.x;
    int d = idx & 127;
    int s = (idx >> 7) & (S_LEN - 1);
    int kvb = idx >> 18;
    int kv = kvb & 3;
    int b = kvb >> 2;
    out[idx] = lin[((size_t)(b * S_LEN + s)) * (NKV * HD) + kv * HD + d];
}

// ---------------- TF32 tensor-core flash attention (causal, GQA) ----------------
// BQ=128, BK=64. 256 threads = 8 warps; warp w owns q rows [w*16, w*16+16).
// Online softmax fully register-resident (stats per thread-quad, shfl reduce).
// Smem floats: Qs 128x132, Ks 64x132, Vs 64x132, Ps 8x(16x68).
#define AQ_STR 132
#define AP_STR 68
#define ATT_SMEM_FLOATS (128*AQ_STR + 64*AQ_STR + 64*AQ_STR + 8*16*AP_STR)

__global__ __launch_bounds__(256) void attn_tf32(const float* __restrict__ Q,
    const float* __restrict__ K, const float* __restrict__ V, float* __restrict__ Out) {
    extern __shared__ float smf[];
    float* Qs = smf;                       // [128][132]
    float* Ks = Qs + 128 * AQ_STR;         // [64][132]
    float* Vs = Ks + 64 * AQ_STR;          // [64][132]
    float* Ps = Vs + 64 * AQ_STR;          // [8][16][68]

    const int qt = (int)gridDim.x - 1 - (int)blockIdx.x;  // heavy tiles first
    const int h  = blockIdx.y;
    const int b  = blockIdx.z;
    const int kvh = h >> 2;
    const int tid = threadIdx.x;
    const int lane = tid & 31, w = tid >> 5;
    const int g = lane >> 2, t = lane & 3;
    const float scale = 0.08838834764831845f;   // 1/sqrt(128)

    const float* Qg = Q + (((size_t)(b * NH + h)) * S_LEN + qt * 128) * HD;
    const float* Kg = K + ((size_t)(b * NKV + kvh)) * S_LEN * HD;
    const float* Vg = V + ((size_t)(b * NKV + kvh)) * S_LEN * HD;

    // load Q tile (tf32-converted), [q][d]
#pragma unroll
    for (int it = 0; it < 16; it++) {
        int i4 = tid + it * 256;
        int r = i4 >> 5, c = (i4 & 31) << 2;
        float4 v = *(const float4*)(Qg + (size_t)r * HD + c);
        float* d = Qs + r * AQ_STR + c;
        d[0] = f2tf32f(v.x); d[1] = f2tf32f(v.y);
        d[2] = f2tf32f(v.z); d[3] = f2tf32f(v.w);
    }

    float o[16][4];
#pragma unroll
    for (int ni = 0; ni < 16; ni++)
#pragma unroll
        for (int r = 0; r < 4; r++) o[ni][r] = 0.f;

    float m0 = -1e30f, m1 = -1e30f, l0 = 0.f, l1 = 0.f;
    const int q0 = qt * 128 + w * 16 + g;
    const int q1 = q0 + 8;
    float* Pw = Ps + w * 16 * AP_STR;

    const int nkt = 2 * qt + 2;
    for (int kt = 0; kt < nkt; kt++) {
        if (kt) __syncthreads();           // all warps done with previous K/V
        // load K,V tiles [k][d], tf32-converted
#pragma unroll
        for (int it = 0; it < 8; it++) {
            int i4 = tid + it * 256;
            int r = i4 >> 5, c = (i4 & 31) << 2;
            float4 kv = *(const float4*)(Kg + (size_t)(kt * 64 + r) * HD + c);
            float* dk = Ks + r * AQ_STR + c;
            dk[0] = f2tf32f(kv.x); dk[1] = f2tf32f(kv.y);
            dk[2] = f2tf32f(kv.z); dk[3] = f2tf32f(kv.w);
            float4 vv = *(const float4*)(Vg + (size_t)(kt * 64 + r) * HD + c);
            float* dv = Vs + r * AQ_STR + c;
            dv[0] = f2tf32f(vv.x); dv[1] = f2tf32f(vv.y);
            dv[2] = f2tf32f(vv.z); dv[3] = f2tf32f(vv.w);
        }
        __syncthreads();

        // ---- S = Q K^T : warp computes 16x64 ----
        float sfr[8][4];
#pragma unroll
        for (int ni = 0; ni < 8; ni++)
#pragma unroll
            for (int r = 0; r < 4; r++) sfr[ni][r] = 0.f;

#pragma unroll
        for (int kk = 0; kk < 16; kk++) {
            const float* qr = Qs + (w * 16 + g) * AQ_STR + kk * 8 + t;
            uint32_t a0 = __float_as_uint(qr[0]);
            uint32_t a1 = __float_as_uint(qr[8 * AQ_STR]);
            uint32_t a2 = __float_as_uint(qr[4]);
            uint32_t a3 = __float_as_uint(qr[8 * AQ_STR + 4]);
#pragma unroll
            for (int ni = 0; ni < 8; ni++) {
                const float* kr = Ks + (ni * 8 + g) * AQ_STR + kk * 8 + t;
                mma_tf32(sfr[ni], a0, a1, a2, a3,
                         __float_as_uint(kr[0]), __float_as_uint(kr[4]));
            }
        }

        // ---- mask + scale ----
        const bool nm = (kt >= 2 * qt);    // only diagonal-straddling tiles
#pragma unroll
        for (int ni = 0; ni < 8; ni++) {
            int kb = kt * 64 + ni * 8 + 2 * t;
            float s0 = sfr[ni][0] * scale, s1 = sfr[ni][1] * scale;
            float s2 = sfr[ni][2] * scale, s3 = sfr[ni][3] * scale;
            if (nm) {
                if (kb     > q0) s0 = -1e30f;
                if (kb + 1 > q0) s1 = -1e30f;
                if (kb     > q1) s2 = -1e30f;
                if (kb + 1 > q1) s3 = -1e30f;
            }
            sfr[ni][0] = s0; sfr[ni][1] = s1; sfr[ni][2] = s2; sfr[ni][3] = s3;
        }

        // ---- online softmax (register-resident; quad shfl reduce) ----
        float mn0 = -1e30f, mn1 = -1e30f;
#pragma unroll
        for (int ni = 0; ni < 8; ni++) {
            mn0 = fmaxf(mn0, fmaxf(sfr[ni][0], sfr[ni][1]));
            mn1 = fmaxf(mn1, fmaxf(sfr[ni][2], sfr[ni][3]));
        }
        mn0 = fmaxf(mn0, __shfl_xor_sync(0xffffffffu, mn0, 1));
        mn0 = fmaxf(mn0, __shfl_xor_sync(0xffffffffu, mn0, 2));
        mn1 = fmaxf(mn1, __shfl_xor_sync(0xffffffffu, mn1, 1));
        mn1 = fmaxf(mn1, __shfl_xor_sync(0xffffffffu, mn1, 2));

        float nmx0 = fmaxf(m0, mn0), nmx1 = fmaxf(m1, mn1);
        float al0 = __expf(m0 - nmx0), al1 = __expf(m1 - nmx1);
        m0 = nmx0; m1 = nmx1;

        __syncwarp();   // previous PV reads of Pw done before overwrite
        float sum0 = 0.f, sum1 = 0.f;
#pragma unroll
        for (int ni = 0; ni < 8; ni++) {
            float p0 = __expf(sfr[ni][0] - m0);
            float p1 = __expf(sfr[ni][1] - m0);
            float p2 = __expf(sfr[ni][2] - m1);
            float p3 = __expf(sfr[ni][3] - m1);
            sum0 += p0 + p1; sum1 += p2 + p3;
            int c = ni * 8 + 2 * t;
            Pw[g * AP_STR + c]           = f2tf32f(p0);
            Pw[g * AP_STR + c + 1]       = f2tf32f(p1);
            Pw[(g + 8) * AP_STR + c]     = f2tf32f(p2);
            Pw[(g + 8) * AP_STR + c + 1] = f2tf32f(p3);
        }
        sum0 += __shfl_xor_sync(0xffffffffu, sum0, 1);
        sum0 += __shfl_xor_sync(0xffffffffu, sum0, 2);
        sum1 += __shfl_xor_sync(0xffffffffu, sum1, 1);
        sum1 += __shfl_xor_sync(0xffffffffu, sum1, 2);
        l0 = l0 * al0 + sum0;
        l1 = l1 * al1 + sum1;

#pragma unroll
        for (int ni = 0; ni < 16; ni++) {
            o[ni][0] *= al0; o[ni][1] *= al0;
            o[ni][2] *= al1; o[ni][3] *= al1;
        }
        __syncwarp();   // Pw writes visible to all lanes

        // ---- O += P V : warp computes 16x128 ----
#pragma unroll
        for (int kk = 0; kk < 8; kk++) {
            const float* pr = Pw + g * AP_STR + kk * 8 + t;
            uint32_t a0 = __float_as_uint(pr[0]);
            uint32_t a1 = __float_as_uint(pr[8 * AP_STR]);
            uint32_t a2 = __float_as_uint(pr[4]);
            uint32_t a3 = __float_as_uint(pr[8 * AP_STR + 4]);
#pragma unroll
            for (int ni = 0; ni < 16; ni++) {
                const float* vr = Vs + (kk * 8 + t) * AQ_STR + ni * 8 + g;
                mma_tf32(o[ni], a0, a1, a2, a3,
                         __float_as_uint(vr[0]), __float_as_uint(vr[4 * AQ_STR]));
            }
        }
    }

    // ---- epilogue: normalize and write [b, q, h*HD + d] ----
    float inv0 = 1.f / l0, inv1 = 1.f / l1;
    size_t ro0 = ((size_t)(b * S_LEN) + q0) * DM + h * HD;
    size_t ro1 = ((size_t)(b * S_LEN) + q1) * DM + h * HD;
#pragma unroll
    for (int ni = 0; ni < 16; ni++) {
        int c = ni * 8 + 2 * t;
        *(float2*)(Out + ro0 + c) = make_float2(o[ni][0] * inv0, o[ni][1] * inv0);
        *(float2*)(Out + ro1 + c) = make_float2(o[ni][2] * inv1, o[ni][3] * inv1);
    }
}

// ---------------- launch ----------------
extern "C" void kernel_launch(void* const* d_in, const int* in_sizes, int n_in,
                              void* d_out, int out_size) {
    const float* x  = (const float*)d_in[0];
    const float* rc = (const float*)d_in[1];
    const float* rs = (const float*)d_in[2];
    const float* Wq = (const float*)d_in[3];
    const float* Wk = (const float*)d_in[4];
    const float* Wv = (const float*)d_in[5];
    const float* Wo = (const float*)d_in[6];
    float* out = (float*)d_out;

    float *qlin, *klin, *vlin, *q, *k, *v, *att;
    cudaGetSymbolAddress((void**)&qlin, g_qlin);
    cudaGetSymbolAddress((void**)&klin, g_klin);
    cudaGetSymbolAddress((void**)&vlin, g_vlin);
    cudaGetSymbolAddress((void**)&q,    g_q);
    cudaGetSymbolAddress((void**)&k,    g_k);
    cudaGetSymbolAddress((void**)&v,    g_v);
    cudaGetSymbolAddress((void**)&att,  g_att);

    const int ATT_SMEM = ATT_SMEM_FLOATS * 4;
    cudaFuncSetAttribute(attn_tf32, cudaFuncAttributeMaxDynamicSharedMemorySize, ATT_SMEM);

    const int M = 2 * S_LEN;  // 4096

    // projections (TF32 tensor cores)
    tf32_gemm<<<dim3(2048 / 128, M / 128), 256>>>(M, 2048, 2048, x, Wq, qlin);
    tf32_gemm<<<dim3(512 / 128,  M / 128), 256>>>(M, 512,  2048, x, Wk, klin);
    tf32_gemm<<<dim3(512 / 128,  M / 128), 256>>>(M, 512,  2048, x, Wv, vlin);

    // rope + relayout
    rope_kernel<<<(2 * NH  * S_LEN * 64) / 256, 256>>>(qlin, rc, rs, q, NH);
    rope_kernel<<<(2 * NKV * S_LEN * 64) / 256, 256>>>(klin, rc, rs, k, NKV);
    vtrans_kernel<<<(2 * NKV * S_LEN * 128) / 256, 256>>>(vlin, v);

    // attention (TF32 tensor cores)
    attn_tf32<<<dim3(S_LEN / 128, NH, 2), 256, ATT_SMEM>>>(q, k, v, att);

    // output projection (TF32 tensor cores)
    tf32_gemm<<<dim3(2048 / 128, M / 128), 256>>>(M, 2048, 2048, att, Wo, out);
}

// round 12
// speedup vs baseline: 3.4748x; 1.1530x over previous
#include <cuda_runtime.h>
#include <cstdint>
#include <math.h>

#define S_LEN 2048
#define DM    2048
#define NH    16
#define NKV   4
#define HD    128

// ---------------- scratch (device globals; no runtime allocation) ----------------
__device__ float g_qlin[4096u * 2048u];
__device__ float g_klin[4096u * 512u];
__device__ float g_vlin[4096u * 512u];
__device__ float g_q[4096u * 2048u];
__device__ float g_k[2u * 4u * 2048u * 128u];
__device__ float g_v[2u * 4u * 2048u * 128u];
__device__ float g_att[4096u * 2048u];
// tf32-pre-rounded copies of GEMM inputs (so cp.async + mma truncation == rna rounding)
__device__ float g_xr[4096u * 2048u];
__device__ float g_wq[2048u * 2048u];
__device__ float g_wk[2048u * 512u];
__device__ float g_wv[2048u * 512u];
__device__ float g_wo[2048u * 2048u];

// ---------------- helpers ----------------
__device__ __forceinline__ uint32_t f2tf32(float x) {
    uint32_t r;
    asm("cvt.rna.tf32.f32 %0, %1;" : "=r"(r) : "f"(x));
    return r;
}
__device__ __forceinline__ float f2tf32f(float x) { return __uint_as_float(f2tf32(x)); }

__device__ __forceinline__ void mma_tf32(float c[4], uint32_t a0, uint32_t a1,
                                         uint32_t a2, uint32_t a3,
                                         uint32_t b0, uint32_t b1) {
    asm volatile(
        "mma.sync.aligned.m16n8k8.row.col.f32.tf32.tf32.f32 "
        "{%0,%1,%2,%3}, {%4,%5,%6,%7}, {%8,%9}, {%0,%1,%2,%3};\n"
        : "+f"(c[0]), "+f"(c[1]), "+f"(c[2]), "+f"(c[3])
        : "r"(a0), "r"(a1), "r"(a2), "r"(a3), "r"(b0), "r"(b1));
}

__device__ __forceinline__ void cp16(float* smem_dst, const float* gmem_src) {
    uint32_t s = (uint32_t)__cvta_generic_to_shared(smem_dst);
    asm volatile("cp.async.cg.shared.global [%0], [%1], 16;\n" :: "r"(s), "l"(gmem_src));
}

// ---------------- tf32 pre-round (elementwise, float4) ----------------
__global__ void round_tf32(const float* __restrict__ src, float* __restrict__ dst, int n4) {
    int i = blockIdx.x * blockDim.x + threadIdx.x;
    if (i < n4) {
        float4 v = ((const float4*)src)[i];
        v.x = f2tf32f(v.x); v.y = f2tf32f(v.y);
        v.z = f2tf32f(v.z); v.w = f2tf32f(v.w);
        ((float4*)dst)[i] = v;
    }
}

// ---------------- TF32 GEMM body: C[128x128 tile] = A*B, cp.async double-buffered ----
// Inputs MUST be tf32-pre-rounded fp32 (mma truncation is then lossless).
#define GS_A   (128 * 36)
#define GS_B   (32 * 136)
#define GS_ST  (GS_A + GS_B)                 // floats per stage
#define GEMM_SMEM_BYTES (2 * GS_ST * 4)      // 71680

__device__ __forceinline__ void gemm_body(int N, int K,
    const float* __restrict__ A, const float* __restrict__ B, float* __restrict__ C,
    int bx, int by, float* sm) {
    const int tid  = threadIdx.x;
    const int lane = tid & 31, wid = tid >> 5;
    const int g = lane >> 2, t = lane & 3;
    const int wm = (wid >> 2) * 64, wn = (wid & 3) * 32;

    A += (size_t)by * 128 * K;
    B += (size_t)bx * 128;
    C += (size_t)by * 128 * N + (size_t)bx * 128;

    float acc[4][4][4];
#pragma unroll
    for (int mi = 0; mi < 4; mi++)
#pragma unroll
        for (int ni = 0; ni < 4; ni++)
#pragma unroll
            for (int r = 0; r < 4; r++) acc[mi][ni][r] = 0.f;

    const int niter = K >> 5;

    // prologue: stage 0
    {
        float* As = sm; float* Bs = sm + GS_A;
#pragma unroll
        for (int it = 0; it < 4; it++) {
            int idx = tid + it * 256;
            int r = idx >> 3, c4 = (idx & 7) << 2;
            cp16(As + r * 36 + c4, A + (size_t)r * K + c4);
        }
#pragma unroll
        for (int it = 0; it < 4; it++) {
            int idx = tid + it * 256;
            int r = idx >> 5, c4 = (idx & 31) << 2;
            cp16(Bs + r * 136 + c4, B + (size_t)r * N + c4);
        }
        asm volatile("cp.async.commit_group;\n");
    }

    for (int i = 0; i < niter; i++) {
        float* As = sm + (i & 1) * GS_ST;
        float* Bs = As + GS_A;
        if (i + 1 < niter) {
            float* An = sm + ((i + 1) & 1) * GS_ST;
            float* Bn = An + GS_A;
            int k0 = (i + 1) << 5;
#pragma unroll
            for (int it = 0; it < 4; it++) {
                int idx = tid + it * 256;
                int r = idx >> 3, c4 = (idx & 7) << 2;
                cp16(An + r * 36 + c4, A + (size_t)r * K + k0 + c4);
            }
#pragma unroll
            for (int it = 0; it < 4; it++) {
                int idx = tid + it * 256;
                int r = idx >> 5, c4 = (idx & 31) << 2;
                cp16(Bn + r * 136 + c4, B + (size_t)(k0 + r) * N + c4);
            }
            asm volatile("cp.async.commit_group;\n");
            asm volatile("cp.async.wait_group 1;\n");
        } else {
            asm volatile("cp.async.wait_group 0;\n");
        }
        __syncthreads();

#pragma unroll
        for (int kk = 0; kk < 32; kk += 8) {
            uint32_t af[4][4], bf[4][2];
#pragma unroll
            for (int mi = 0; mi < 4; mi++) {
                const float* ar = As + (wm + mi * 16 + g) * 36 + kk + t;
                af[mi][0] = __float_as_uint(ar[0]);
                af[mi][1] = __float_as_uint(ar[8 * 36]);
                af[mi][2] = __float_as_uint(ar[4]);
                af[mi][3] = __float_as_uint(ar[8 * 36 + 4]);
            }
#pragma unroll
            for (int ni = 0; ni < 4; ni++) {
                const float* br = Bs + (kk + t) * 136 + wn + ni * 8 + g;
                bf[ni][0] = __float_as_uint(br[0]);
                bf[ni][1] = __float_as_uint(br[4 * 136]);
            }
#pragma unroll
            for (int mi = 0; mi < 4; mi++)
#pragma unroll
                for (int ni = 0; ni < 4; ni++)
                    mma_tf32(acc[mi][ni], af[mi][0], af[mi][1], af[mi][2], af[mi][3],
                             bf[ni][0], bf[ni][1]);
        }
        __syncthreads();
    }

#pragma unroll
    for (int mi = 0; mi < 4; mi++) {
#pragma unroll
        for (int ni = 0; ni < 4; ni++) {
            int row = wm + mi * 16 + g;
            int col = wn + ni * 8 + 2 * t;
            *(float2*)(C + (size_t)row * N + col) =
                make_float2(acc[mi][ni][0], acc[mi][ni][1]);
            *(float2*)(C + (size_t)(row + 8) * N + col) =
                make_float2(acc[mi][ni][2], acc[mi][ni][3]);
        }
    }
}

// Merged QKV projection: grid.x = 24 (16 Wq tiles + 4 Wk + 4 Wv), grid.y = 32.
__global__ __launch_bounds__(256, 2) void qkv_gemm(
    const float* __restrict__ x,
    const float* __restrict__ Wq, const float* __restrict__ Wk, const float* __restrict__ Wv,
    float* __restrict__ qlin, float* __restrict__ klin, float* __restrict__ vlin) {
    extern __shared__ float sm[];
    int bx = blockIdx.x;
    const float* B; float* C; int N, nbx;
    if (bx < 16)      { B = Wq; C = qlin; N = 2048; nbx = bx; }
    else if (bx < 20) { B = Wk; C = klin; N = 512;  nbx = bx - 16; }
    else              { B = Wv; C = vlin; N = 512;  nbx = bx - 20; }
    gemm_body(N, 2048, x, B, C, nbx, blockIdx.y, sm);
}

__global__ __launch_bounds__(256, 2) void out_gemm(
    const float* __restrict__ A, const float* __restrict__ B, float* __restrict__ C) {
    extern __shared__ float sm[];
    gemm_body(2048, 2048, A, B, C, blockIdx.x, blockIdx.y, sm);
}

// ---------------- RoPE + [B,S,h*HD] -> [B,h,S,HD] relayout ----------------
__global__ void rope_kernel(const float* __restrict__ lin, const float* __restrict__ cosv,
                            const float* __restrict__ sinv, float* __restrict__ out, int nh) {
    int idx = blockIdx.x * blockDim.x + threadIdx.x;
    int i = idx & 63;
    int s = (idx >> 6) & (S_LEN - 1);
    int bh = idx >> 17;
    int h = bh % nh;
    int b = bh / nh;

    float c  = cosv[s * 64 + i];
    float sn = sinv[s * 64 + i];
    const float* src = lin + ((size_t)(b * S_LEN + s)) * (nh * HD) + h * HD + 2 * i;
    float e = src[0], o = src[1];
    float* dst = out + (((size_t)bh) * S_LEN + s) * HD + 2 * i;
    dst[0] = e * c - o * sn;
    dst[1] = e * sn + o * c;
}

// ---------------- V relayout [B,S,kv*HD] -> [B,kv,S,HD] ----------------
__global__ void vtrans_kernel(const float* __restrict__ lin, float* __restrict__ out) {
    int idx = blockIdx.x * blockDim.x + threadIdx.x;
    int d = idx & 127;
    int s = (idx >> 7) & (S_LEN - 1);
    int kvb = idx >> 18;
    int kv = kvb & 3;
    int b = kvb >> 2;
    out[idx] = lin[((size_t)(b * S_LEN + s)) * (NKV * HD) + kv * HD + d];
}

// ---------------- TF32 tensor-core flash attention (causal, GQA) ----------------
#define AQ_STR 132
#define AP_STR 68
#define ATT_SMEM_FLOATS (128*AQ_STR + 64*AQ_STR + 64*AQ_STR + 8*16*AP_STR)

__global__ __launch_bounds__(256) void attn_tf32(const float* __restrict__ Q,
    const float* __restrict__ K, const float* __restrict__ V, float* __restrict__ Out) {
    extern __shared__ float smf[];
    float* Qs = smf;
    float* Ks = Qs + 128 * AQ_STR;
    float* Vs = Ks + 64 * AQ_STR;
    float* Ps = Vs + 64 * AQ_STR;

    const int qt = (int)gridDim.x - 1 - (int)blockIdx.x;
    const int h  = blockIdx.y;
    const int b  = blockIdx.z;
    const int kvh = h >> 2;
    const int tid = threadIdx.x;
    const int lane = tid & 31, w = tid >> 5;
    const int g = lane >> 2, t = lane & 3;
    const float scale = 0.08838834764831845f;

    const float* Qg = Q + (((size_t)(b * NH + h)) * S_LEN + qt * 128) * HD;
    const float* Kg = K + ((size_t)(b * NKV + kvh)) * S_LEN * HD;
    const float* Vg = V + ((size_t)(b * NKV + kvh)) * S_LEN * HD;

#pragma unroll
    for (int it = 0; it < 16; it++) {
        int i4 = tid + it * 256;
        int r = i4 >> 5, c = (i4 & 31) << 2;
        float4 v = *(const float4*)(Qg + (size_t)r * HD + c);
        float* d = Qs + r * AQ_STR + c;
        d[0] = f2tf32f(v.x); d[1] = f2tf32f(v.y);
        d[2] = f2tf32f(v.z); d[3] = f2tf32f(v.w);
    }

    float o[16][4];
#pragma unroll
    for (int ni = 0; ni < 16; ni++)
#pragma unroll
        for (int r = 0; r < 4; r++) o[ni][r] = 0.f;

    float m0 = -1e30f, m1 = -1e30f, l0 = 0.f, l1 = 0.f;
    const int q0 = qt * 128 + w * 16 + g;
    const int q1 = q0 + 8;
    float* Pw = Ps + w * 16 * AP_STR;

    const int nkt = 2 * qt + 2;
    for (int kt = 0; kt < nkt; kt++) {
        if (kt) __syncthreads();
#pragma unroll
        for (int it = 0; it < 8; it++) {
            int i4 = tid + it * 256;
            int r = i4 >> 5, c = (i4 & 31) << 2;
            float4 kv = *(const float4*)(Kg + (size_t)(kt * 64 + r) * HD + c);
            float* dk = Ks + r * AQ_STR + c;
            dk[0] = f2tf32f(kv.x); dk[1] = f2tf32f(kv.y);
            dk[2] = f2tf32f(kv.z); dk[3] = f2tf32f(kv.w);
            float4 vv = *(const float4*)(Vg + (size_t)(kt * 64 + r) * HD + c);
            float* dv = Vs + r * AQ_STR + c;
            dv[0] = f2tf32f(vv.x); dv[1] = f2tf32f(vv.y);
            dv[2] = f2tf32f(vv.z); dv[3] = f2tf32f(vv.w);
        }
        __syncthreads();

        float sfr[8][4];
#pragma unroll
        for (int ni = 0; ni < 8; ni++)
#pragma unroll
            for (int r = 0; r < 4; r++) sfr[ni][r] = 0.f;

#pragma unroll
        for (int kk = 0; kk < 16; kk++) {
            const float* qr = Qs + (w * 16 + g) * AQ_STR + kk * 8 + t;
            uint32_t a0 = __float_as_uint(qr[0]);
            uint32_t a1 = __float_as_uint(qr[8 * AQ_STR]);
            uint32_t a2 = __float_as_uint(qr[4]);
            uint32_t a3 = __float_as_uint(qr[8 * AQ_STR + 4]);
#pragma unroll
            for (int ni = 0; ni < 8; ni++) {
                const float* kr = Ks + (ni * 8 + g) * AQ_STR + kk * 8 + t;
                mma_tf32(sfr[ni], a0, a1, a2, a3,
                         __float_as_uint(kr[0]), __float_as_uint(kr[4]));
            }
        }

        const bool nm = (kt >= 2 * qt);
#pragma unroll
        for (int ni = 0; ni < 8; ni++) {
            int kb = kt * 64 + ni * 8 + 2 * t;
            float s0 = sfr[ni][0] * scale, s1 = sfr[ni][1] * scale;
            float s2 = sfr[ni][2] * scale, s3 = sfr[ni][3] * scale;
            if (nm) {
                if (kb     > q0) s0 = -1e30f;
                if (kb + 1 > q0) s1 = -1e30f;
                if (kb     > q1) s2 = -1e30f;
                if (kb + 1 > q1) s3 = -1e30f;
            }
            sfr[ni][0] = s0; sfr[ni][1] = s1; sfr[ni][2] = s2; sfr[ni][3] = s3;
        }

        float mn0 = -1e30f, mn1 = -1e30f;
#pragma unroll
        for (int ni = 0; ni < 8; ni++) {
            mn0 = fmaxf(mn0, fmaxf(sfr[ni][0], sfr[ni][1]));
            mn1 = fmaxf(mn1, fmaxf(sfr[ni][2], sfr[ni][3]));
        }
        mn0 = fmaxf(mn0, __shfl_xor_sync(0xffffffffu, mn0, 1));
        mn0 = fmaxf(mn0, __shfl_xor_sync(0xffffffffu, mn0, 2));
        mn1 = fmaxf(mn1, __shfl_xor_sync(0xffffffffu, mn1, 1));
        mn1 = fmaxf(mn1, __shfl_xor_sync(0xffffffffu, mn1, 2));

        float nmx0 = fmaxf(m0, mn0), nmx1 = fmaxf(m1, mn1);
        float al0 = __expf(m0 - nmx0), al1 = __expf(m1 - nmx1);
        m0 = nmx0; m1 = nmx1;

        __syncwarp();
        float sum0 = 0.f, sum1 = 0.f;
#pragma unroll
        for (int ni = 0; ni < 8; ni++) {
            float p0 = __expf(sfr[ni][0] - m0);
            float p1 = __expf(sfr[ni][1] - m0);
            float p2 = __expf(sfr[ni][2] - m1);
            float p3 = __expf(sfr[ni][3] - m1);
            sum0 += p0 + p1; sum1 += p2 + p3;
            int c = ni * 8 + 2 * t;
            Pw[g * AP_STR + c]           = f2tf32f(p0);
            Pw[g * AP_STR + c + 1]       = f2tf32f(p1);
            Pw[(g + 8) * AP_STR + c]     = f2tf32f(p2);
            Pw[(g + 8) * AP_STR + c + 1] = f2tf32f(p3);
        }
        sum0 += __shfl_xor_sync(0xffffffffu, sum0, 1);
        sum0 += __shfl_xor_sync(0xffffffffu, sum0, 2);
        sum1 += __shfl_xor_sync(0xffffffffu, sum1, 1);
        sum1 += __shfl_xor_sync(0xffffffffu, sum1, 2);
        l0 = l0 * al0 + sum0;
        l1 = l1 * al1 + sum1;

#pragma unroll
        for (int ni = 0; ni < 16; ni++) {
            o[ni][0] *= al0; o[ni][1] *= al0;
            o[ni][2] *= al1; o[ni][3] *= al1;
        }
        __syncwarp();

#pragma unroll
        for (int kk = 0; kk < 8; kk++) {
            const float* pr = Pw + g * AP_STR + kk * 8 + t;
            uint32_t a0 = __float_as_uint(pr[0]);
            uint32_t a1 = __float_as_uint(pr[8 * AP_STR]);
            uint32_t a2 = __float_as_uint(pr[4]);
            uint32_t a3 = __float_as_uint(pr[8 * AP_STR + 4]);
#pragma unroll
            for (int ni = 0; ni < 16; ni++) {
                const float* vr = Vs + (kk * 8 + t) * AQ_STR + ni * 8 + g;
                mma_tf32(o[ni], a0, a1, a2, a3,
                         __float_as_uint(vr[0]), __float_as_uint(vr[4 * AQ_STR]));
            }
        }
    }

    // epilogue: rna-round outputs so the Wo GEMM's truncation is lossless
    float inv0 = 1.f / l0, inv1 = 1.f / l1;
    size_t ro0 = ((size_t)(b * S_LEN) + q0) * DM + h * HD;
    size_t ro1 = ((size_t)(b * S_LEN) + q1) * DM + h * HD;
#pragma unroll
    for (int ni = 0; ni < 16; ni++) {
        int c = ni * 8 + 2 * t;
        *(float2*)(Out + ro0 + c) =
            make_float2(f2tf32f(o[ni][0] * inv0), f2tf32f(o[ni][1] * inv0));
        *(float2*)(Out + ro1 + c) =
            make_float2(f2tf32f(o[ni][2] * inv1), f2tf32f(o[ni][3] * inv1));
    }
}

// ---------------- launch ----------------
extern "C" void kernel_launch(void* const* d_in, const int* in_sizes, int n_in,
                              void* d_out, int out_size) {
    const float* x  = (const float*)d_in[0];
    const float* rc = (const float*)d_in[1];
    const float* rs = (const float*)d_in[2];
    const float* Wq = (const float*)d_in[3];
    const float* Wk = (const float*)d_in[4];
    const float* Wv = (const float*)d_in[5];
    const float* Wo = (const float*)d_in[6];
    float* out = (float*)d_out;

    float *qlin, *klin, *vlin, *q, *k, *v, *att;
    float *xr, *wq, *wk, *wv, *wo;
    cudaGetSymbolAddress((void**)&qlin, g_qlin);
    cudaGetSymbolAddress((void**)&klin, g_klin);
    cudaGetSymbolAddress((void**)&vlin, g_vlin);
    cudaGetSymbolAddress((void**)&q,    g_q);
    cudaGetSymbolAddress((void**)&k,    g_k);
    cudaGetSymbolAddress((void**)&v,    g_v);
    cudaGetSymbolAddress((void**)&att,  g_att);
    cudaGetSymbolAddress((void**)&xr,   g_xr);
    cudaGetSymbolAddress((void**)&wq,   g_wq);
    cudaGetSymbolAddress((void**)&wk,   g_wk);
    cudaGetSymbolAddress((void**)&wv,   g_wv);
    cudaGetSymbolAddress((void**)&wo,   g_wo);

    const int ATT_SMEM = ATT_SMEM_FLOATS * 4;
    cudaFuncSetAttribute(attn_tf32, cudaFuncAttributeMaxDynamicSharedMemorySize, ATT_SMEM);
    cudaFuncSetAttribute(qkv_gemm, cudaFuncAttributeMaxDynamicSharedMemorySize, GEMM_SMEM_BYTES);
    cudaFuncSetAttribute(out_gemm, cudaFuncAttributeMaxDynamicSharedMemorySize, GEMM_SMEM_BYTES);

    // pre-round GEMM inputs to tf32 (launches 0-4; ncu -s 5 then lands on qkv_gemm)
    round_tf32<<<(4096 * 2048 / 4 + 255) / 256, 256>>>(x,  xr, 4096 * 2048 / 4);
    round_tf32<<<(2048 * 2048 / 4 + 255) / 256, 256>>>(Wq, wq, 2048 * 2048 / 4);
    round_tf32<<<(2048 * 512  / 4 + 255) / 256, 256>>>(Wk, wk, 2048 * 512 / 4);
    round_tf32<<<(2048 * 512  / 4 + 255) / 256, 256>>>(Wv, wv, 2048 * 512 / 4);
    round_tf32<<<(2048 * 2048 / 4 + 255) / 256, 256>>>(Wo, wo, 2048 * 2048 / 4);

    // merged QKV projection (TF32 tensor cores, cp.async double-buffered)
    qkv_gemm<<<dim3(24, 32), 256, GEMM_SMEM_BYTES>>>(xr, wq, wk, wv, qlin, klin, vlin);

    // rope + relayout
    rope_kernel<<<(2 * NH  * S_LEN * 64) / 256, 256>>>(qlin, rc, rs, q, NH);
    rope_kernel<<<(2 * NKV * S_LEN * 64) / 256, 256>>>(klin, rc, rs, k, NKV);
    vtrans_kernel<<<(2 * NKV * S_LEN * 128) / 256, 256>>>(vlin, v);

    // attention (TF32 tensor cores)
    attn_tf32<<<dim3(S_LEN / 128, NH, 2), 256, ATT_SMEM>>>(q, k, v, att);

    // output projection
    out_gemm<<<dim3(16, 32), 256, GEMM_SMEM_BYTES>>>(att, wo, out);
}

// round 14
// speedup vs baseline: 3.6619x; 1.0538x over previous
#include <cuda_runtime.h>
#include <cstdint>
#include <math.h>

#define S_LEN 2048
#define DM    2048
#define NH    16
#define NKV   4
#define HD    128

// ---------------- scratch (device globals; no runtime allocation) ----------------
__device__ float g_qlin[4096u * 2048u];
__device__ float g_klin[4096u * 512u];
__device__ float g_vlin[4096u * 512u];
__device__ float g_q[4096u * 2048u];
__device__ float g_k[2u * 4u * 2048u * 128u];
__device__ float g_v[2u * 4u * 2048u * 128u];
__device__ float g_att[4096u * 2048u];
// tf32-pre-rounded copies of GEMM inputs (so cp.async + mma truncation == rna rounding)
__device__ float g_xr[4096u * 2048u];
__device__ float g_wq[2048u * 2048u];
__device__ float g_wk[2048u * 512u];
__device__ float g_wv[2048u * 512u];
__device__ float g_wo[2048u * 2048u];

// ---------------- helpers ----------------
__device__ __forceinline__ uint32_t f2tf32(float x) {
    uint32_t r;
    asm("cvt.rna.tf32.f32 %0, %1;" : "=r"(r) : "f"(x));
    return r;
}
__device__ __forceinline__ float f2tf32f(float x) { return __uint_as_float(f2tf32(x)); }

__device__ __forceinline__ void mma_tf32(float c[4], uint32_t a0, uint32_t a1,
                                         uint32_t a2, uint32_t a3,
                                         uint32_t b0, uint32_t b1) {
    asm volatile(
        "mma.sync.aligned.m16n8k8.row.col.f32.tf32.tf32.f32 "
        "{%0,%1,%2,%3}, {%4,%5,%6,%7}, {%8,%9}, {%0,%1,%2,%3};\n"
        : "+f"(c[0]), "+f"(c[1]), "+f"(c[2]), "+f"(c[3])
        : "r"(a0), "r"(a1), "r"(a2), "r"(a3), "r"(b0), "r"(b1));
}

__device__ __forceinline__ void cp16(float* smem_dst, const float* gmem_src) {
    uint32_t s = (uint32_t)__cvta_generic_to_shared(smem_dst);
    asm volatile("cp.async.cg.shared.global [%0], [%1], 16;\n" :: "r"(s), "l"(gmem_src));
}

// ---------------- tf32 pre-round (elementwise, float4) ----------------
__global__ void round_tf32(const float* __restrict__ src, float* __restrict__ dst, int n4) {
    int i = blockIdx.x * blockDim.x + threadIdx.x;
    if (i < n4) {
        float4 v = ((const float4*)src)[i];
        v.x = f2tf32f(v.x); v.y = f2tf32f(v.y);
        v.z = f2tf32f(v.z); v.w = f2tf32f(v.w);
        ((float4*)dst)[i] = v;
    }
}

// ---------------- TF32 GEMM body: C[128x128 tile] = A*B, cp.async double-buffered ----
// Inputs MUST be tf32-pre-rounded fp32 (mma truncation is then lossless).
#define GS_A   (128 * 36)
#define GS_B   (32 * 136)
#define GS_ST  (GS_A + GS_B)                 // floats per stage
#define GEMM_SMEM_BYTES (2 * GS_ST * 4)      // 71680

__device__ __forceinline__ void gemm_body(int N, int K,
    const float* __restrict__ A, const float* __restrict__ B, float* __restrict__ C,
    int bx, int by, float* sm) {
    const int tid  = threadIdx.x;
    const int lane = tid & 31, wid = tid >> 5;
    const int g = lane >> 2, t = lane & 3;
    const int wm = (wid >> 2) * 64, wn = (wid & 3) * 32;

    A += (size_t)by * 128 * K;
    B += (size_t)bx * 128;
    C += (size_t)by * 128 * N + (size_t)bx * 128;

    float acc[4][4][4];
#pragma unroll
    for (int mi = 0; mi < 4; mi++)
#pragma unroll
        for (int ni = 0; ni < 4; ni++)
#pragma unroll
            for (int r = 0; r < 4; r++) acc[mi][ni][r] = 0.f;

    const int niter = K >> 5;

    // prologue: stage 0
    {
        float* As = sm; float* Bs = sm + GS_A;
#pragma unroll
        for (int it = 0; it < 4; it++) {
            int idx = tid + it * 256;
            int r = idx >> 3, c4 = (idx & 7) << 2;
            cp16(As + r * 36 + c4, A + (size_t)r * K + c4);
        }
#pragma unroll
        for (int it = 0; it < 4; it++) {
            int idx = tid + it * 256;
            int r = idx >> 5, c4 = (idx & 31) << 2;
            cp16(Bs + r * 136 + c4, B + (size_t)r * N + c4);
        }
        asm volatile("cp.async.commit_group;\n");
    }

    for (int i = 0; i < niter; i++) {
        float* As = sm + (i & 1) * GS_ST;
        float* Bs = As + GS_A;
        if (i + 1 < niter) {
            float* An = sm + ((i + 1) & 1) * GS_ST;
            float* Bn = An + GS_A;
            int k0 = (i + 1) << 5;
#pragma unroll
            for (int it = 0; it < 4; it++) {
                int idx = tid + it * 256;
                int r = idx >> 3, c4 = (idx & 7) << 2;
                cp16(An + r * 36 + c4, A + (size_t)r * K + k0 + c4);
            }
#pragma unroll
            for (int it = 0; it < 4; it++) {
                int idx = tid + it * 256;
                int r = idx >> 5, c4 = (idx & 31) << 2;
                cp16(Bn + r * 136 + c4, B + (size_t)(k0 + r) * N + c4);
            }
            asm volatile("cp.async.commit_group;\n");
            asm volatile("cp.async.wait_group 1;\n");
        } else {
            asm volatile("cp.async.wait_group 0;\n");
        }
        __syncthreads();

#pragma unroll
        for (int kk = 0; kk < 32; kk += 8) {
            uint32_t af[4][4], bf[4][2];
#pragma unroll
            for (int mi = 0; mi < 4; mi++) {
                const float* ar = As + (wm + mi * 16 + g) * 36 + kk + t;
                af[mi][0] = __float_as_uint(ar[0]);
                af[mi][1] = __float_as_uint(ar[8 * 36]);
                af[mi][2] = __float_as_uint(ar[4]);
                af[mi][3] = __float_as_uint(ar[8 * 36 + 4]);
            }
#pragma unroll
            for (int ni = 0; ni < 4; ni++) {
                const float* br = Bs + (kk + t) * 136 + wn + ni * 8 + g;
                bf[ni][0] = __float_as_uint(br[0]);
                bf[ni][1] = __float_as_uint(br[4 * 136]);
            }
#pragma unroll
            for (int mi = 0; mi < 4; mi++)
#pragma unroll
                for (int ni = 0; ni < 4; ni++)
                    mma_tf32(acc[mi][ni], af[mi][0], af[mi][1], af[mi][2], af[mi][3],
                             bf[ni][0], bf[ni][1]);
        }
        __syncthreads();
    }

#pragma unroll
    for (int mi = 0; mi < 4; mi++) {
#pragma unroll
        for (int ni = 0; ni < 4; ni++) {
            int row = wm + mi * 16 + g;
            int col = wn + ni * 8 + 2 * t;
            *(float2*)(C + (size_t)row * N + col) =
                make_float2(acc[mi][ni][0], acc[mi][ni][1]);
            *(float2*)(C + (size_t)(row + 8) * N + col) =
                make_float2(acc[mi][ni][2], acc[mi][ni][3]);
        }
    }
}

// Merged QKV projection: grid.x = 24 (16 Wq tiles + 4 Wk + 4 Wv), grid.y = 32.
__global__ __launch_bounds__(256, 2) void qkv_gemm(
    const float* __restrict__ x,
    const float* __restrict__ Wq, const float* __restrict__ Wk, const float* __restrict__ Wv,
    float* __restrict__ qlin, float* __restrict__ klin, float* __restrict__ vlin) {
    extern __shared__ float sm[];
    int bx = blockIdx.x;
    const float* B; float* C; int N, nbx;
    if (bx < 16)      { B = Wq; C = qlin; N = 2048; nbx = bx; }
    else if (bx < 20) { B = Wk; C = klin; N = 512;  nbx = bx - 16; }
    else              { B = Wv; C = vlin; N = 512;  nbx = bx - 20; }
    gemm_body(N, 2048, x, B, C, nbx, blockIdx.y, sm);
}

__global__ __launch_bounds__(256, 2) void out_gemm(
    const float* __restrict__ A, const float* __restrict__ B, float* __restrict__ C) {
    extern __shared__ float sm[];
    gemm_body(2048, 2048, A, B, C, blockIdx.x, blockIdx.y, sm);
}

// ---------------- RoPE + relayout; outputs tf32-pre-rounded for cp.async attention ----
__global__ void rope_kernel(const float* __restrict__ lin, const float* __restrict__ cosv,
                            const float* __restrict__ sinv, float* __restrict__ out, int nh) {
    int idx = blockIdx.x * blockDim.x + threadIdx.x;
    int i = idx & 63;
    int s = (idx >> 6) & (S_LEN - 1);
    int bh = idx >> 17;
    int h = bh % nh;
    int b = bh / nh;

    float c  = cosv[s * 64 + i];
    float sn = sinv[s * 64 + i];
    const float* src = lin + ((size_t)(b * S_LEN + s)) * (nh * HD) + h * HD + 2 * i;
    float e = src[0], o = src[1];
    float* dst = out + (((size_t)bh) * S_LEN + s) * HD + 2 * i;
    dst[0] = f2tf32f(e * c - o * sn);
    dst[1] = f2tf32f(e * sn + o * c);
}

// ---------------- V relayout [B,S,kv*HD] -> [B,kv,S,HD], tf32-pre-rounded ----------------
__global__ void vtrans_kernel(const float* __restrict__ lin, float* __restrict__ out) {
    int idx = blockIdx.x * blockDim.x + threadIdx.x;
    int d = idx & 127;
    int s = (idx >> 7) & (S_LEN - 1);
    int kvb = idx >> 18;
    int kv = kvb & 3;
    int b = kvb >> 2;
    out[idx] = f2tf32f(lin[((size_t)(b * S_LEN + s)) * (NKV * HD) + kv * HD + d]);
}

// ---------------- TF32 tensor-core flash attention (causal, GQA) ----------------
// BQ=128, BK=32, 2-stage cp.async K/V pipeline. Inputs pre-rounded tf32.
// Strides: Q/K 132 (frag bank 4g+t, distinct), V 136 (bank 8t+g, distinct), P 36.
#define AQ_STR 132
#define VS_STR 136
#define PS_STR 36
#define ATT_SMEM_FLOATS (128*AQ_STR + 2*32*AQ_STR + 2*32*VS_STR + 8*16*PS_STR)

__global__ __launch_bounds__(256) void attn_tf32(const float* __restrict__ Q,
    const float* __restrict__ K, const float* __restrict__ V, float* __restrict__ Out) {
    extern __shared__ float smf[];
    float* Qs = smf;                         // [128][132]
    float* Ks = Qs + 128 * AQ_STR;           // 2 stages [32][132]
    float* Vs = Ks + 2 * 32 * AQ_STR;        // 2 stages [32][136]
    float* Ps = Vs + 2 * 32 * VS_STR;        // [8][16][36]

    const int qt = (int)gridDim.x - 1 - (int)blockIdx.x;  // heavy tiles first
    const int h  = blockIdx.y;
    const int b  = blockIdx.z;
    const int kvh = h >> 2;
    const int tid = threadIdx.x;
    const int lane = tid & 31, w = tid >> 5;
    const int g = lane >> 2, t = lane & 3;
    const float scale = 0.08838834764831845f;

    const float* Qg = Q + (((size_t)(b * NH + h)) * S_LEN + qt * 128) * HD;
    const float* Kg = K + ((size_t)(b * NKV + kvh)) * S_LEN * HD;
    const float* Vg = V + ((size_t)(b * NKV + kvh)) * S_LEN * HD;

    // prologue: Q tile + K/V stage 0, one cp.async group
#pragma unroll
    for (int it = 0; it < 16; it++) {
        int i4 = tid + it * 256;
        int r = i4 >> 5, c = (i4 & 31) << 2;
        cp16(Qs + r * AQ_STR + c, Qg + (size_t)r * HD + c);
    }
#pragma unroll
    for (int it = 0; it < 4; it++) {
        int i4 = tid + it * 256;
        int r = i4 >> 5, c = (i4 & 31) << 2;
        cp16(Ks + r * AQ_STR + c, Kg + (size_t)r * HD + c);
        cp16(Vs + r * VS_STR + c, Vg + (size_t)r * HD + c);
    }
    asm volatile("cp.async.commit_group;\n");

    float o[16][4];
#pragma unroll
    for (int ni = 0; ni < 16; ni++)
#pragma unroll
        for (int r = 0; r < 4; r++) o[ni][r] = 0.f;

    float m0 = -1e30f, m1 = -1e30f, l0 = 0.f, l1 = 0.f;
    const int q0 = qt * 128 + w * 16 + g;
    const int q1 = q0 + 8;
    float* Pw = Ps + w * 16 * PS_STR;

    const int nkt = 4 * qt + 4;
    for (int kt = 0; kt < nkt; kt++) {
        float* Kst = Ks + (kt & 1) * 32 * AQ_STR;
        float* Vst = Vs + (kt & 1) * 32 * VS_STR;
        if (kt + 1 < nkt) {
            float* Kn = Ks + ((kt + 1) & 1) * 32 * AQ_STR;
            float* Vn = Vs + ((kt + 1) & 1) * 32 * VS_STR;
            const float* Kgn = Kg + (size_t)(kt + 1) * 32 * HD;
            const float* Vgn = Vg + (size_t)(kt + 1) * 32 * HD;
#pragma unroll
            for (int it = 0; it < 4; it++) {
                int i4 = tid + it * 256;
                int r = i4 >> 5, c = (i4 & 31) << 2;
                cp16(Kn + r * AQ_STR + c, Kgn + (size_t)r * HD + c);
                cp16(Vn + r * VS_STR + c, Vgn + (size_t)r * HD + c);
            }
            asm volatile("cp.async.commit_group;\n");
            asm volatile("cp.async.wait_group 1;\n");
        } else {
            asm volatile("cp.async.wait_group 0;\n");
        }
        __syncthreads();

        // ---- S = Q K^T : warp computes 16x32 ----
        float sfr[4][4];
#pragma unroll
        for (int ni = 0; ni < 4; ni++)
#pragma unroll
            for (int r = 0; r < 4; r++) sfr[ni][r] = 0.f;

#pragma unroll
        for (int kk = 0; kk < 16; kk++) {
            const float* qr = Qs + (w * 16 + g) * AQ_STR + kk * 8 + t;
            uint32_t a0 = __float_as_uint(qr[0]);
            uint32_t a1 = __float_as_uint(qr[8 * AQ_STR]);
            uint32_t a2 = __float_as_uint(qr[4]);
            uint32_t a3 = __float_as_uint(qr[8 * AQ_STR + 4]);
#pragma unroll
            for (int ni = 0; ni < 4; ni++) {
                const float* kr = Kst + (ni * 8 + g) * AQ_STR + kk * 8 + t;
                mma_tf32(sfr[ni], a0, a1, a2, a3,
                         __float_as_uint(kr[0]), __float_as_uint(kr[4]));
            }
        }

        // ---- mask + scale (only tiles straddling the diagonal) ----
        const bool nm = (kt >= 4 * qt);
#pragma unroll
        for (int ni = 0; ni < 4; ni++) {
            int kb = kt * 32 + ni * 8 + 2 * t;
            float s0 = sfr[ni][0] * scale, s1 = sfr[ni][1] * scale;
            float s2 = sfr[ni][2] * scale, s3 = sfr[ni][3] * scale;
            if (nm) {
                if (kb     > q0) s0 = -1e30f;
                if (kb + 1 > q0) s1 = -1e30f;
                if (kb     > q1) s2 = -1e30f;
                if (kb + 1 > q1) s3 = -1e30f;
            }
            sfr[ni][0] = s0; sfr[ni][1] = s1; sfr[ni][2] = s2; sfr[ni][3] = s3;
        }

        // ---- online softmax (register-resident; quad shfl reduce) ----
        float mn0 = -1e30f, mn1 = -1e30f;
#pragma unroll
        for (int ni = 0; ni < 4; ni++) {
            mn0 = fmaxf(mn0, fmaxf(sfr[ni][0], sfr[ni][1]));
            mn1 = fmaxf(mn1, fmaxf(sfr[ni][2], sfr[ni][3]));
        }
        mn0 = fmaxf(mn0, __shfl_xor_sync(0xffffffffu, mn0, 1));
        mn0 = fmaxf(mn0, __shfl_xor_sync(0xffffffffu, mn0, 2));
        mn1 = fmaxf(mn1, __shfl_xor_sync(0xffffffffu, mn1, 1));
        mn1 = fmaxf(mn1, __shfl_xor_sync(0xffffffffu, mn1, 2));

        float nmx0 = fmaxf(m0, mn0), nmx1 = fmaxf(m1, mn1);
        float al0 = __expf(m0 - nmx0), al1 = __expf(m1 - nmx1);
        m0 = nmx0; m1 = nmx1;

        __syncwarp();   // previous PV reads of Pw done before overwrite
        float sum0 = 0.f, sum1 = 0.f;
#pragma unroll
        for (int ni = 0; ni < 4; ni++) {
            float p0 = __expf(sfr[ni][0] - m0);
            float p1 = __expf(sfr[ni][1] - m0);
            float p2 = __expf(sfr[ni][2] - m1);
            float p3 = __expf(sfr[ni][3] - m1);
            sum0 += p0 + p1; sum1 += p2 + p3;
            int c = ni * 8 + 2 * t;
            Pw[g * PS_STR + c]           = f2tf32f(p0);
            Pw[g * PS_STR + c + 1]       = f2tf32f(p1);
            Pw[(g + 8) * PS_STR + c]     = f2tf32f(p2);
            Pw[(g + 8) * PS_STR + c + 1] = f2tf32f(p3);
        }
        sum0 += __shfl_xor_sync(0xffffffffu, sum0, 1);
        sum0 += __shfl_xor_sync(0xffffffffu, sum0, 2);
        sum1 += __shfl_xor_sync(0xffffffffu, sum1, 1);
        sum1 += __shfl_xor_sync(0xffffffffu, sum1, 2);
        l0 = l0 * al0 + sum0;
        l1 = l1 * al1 + sum1;

#pragma unroll
        for (int ni = 0; ni < 16; ni++) {
            o[ni][0] *= al0; o[ni][1] *= al0;
            o[ni][2] *= al1; o[ni][3] *= al1;
        }
        __syncwarp();   // Pw writes visible to all lanes

        // ---- O += P V : warp computes 16x128 ----
#pragma unroll
        for (int kk = 0; kk < 4; kk++) {
            const float* pr = Pw + g * PS_STR + kk * 8 + t;
            uint32_t a0 = __float_as_uint(pr[0]);
            uint32_t a1 = __float_as_uint(pr[8 * PS_STR]);
            uint32_t a2 = __float_as_uint(pr[4]);
            uint32_t a3 = __float_as_uint(pr[8 * PS_STR + 4]);
#pragma unroll
            for (int ni = 0; ni < 16; ni++) {
                const float* vr = Vst + (kk * 8 + t) * VS_STR + ni * 8 + g;
                mma_tf32(o[ni], a0, a1, a2, a3,
                         __float_as_uint(vr[0]), __float_as_uint(vr[4 * VS_STR]));
            }
        }
        __syncthreads();   // stage free before next iteration's prefetch
    }

    // epilogue: rna-round outputs so the Wo GEMM's truncation is lossless
    float inv0 = 1.f / l0, inv1 = 1.f / l1;
    size_t ro0 = ((size_t)(b * S_LEN) + q0) * DM + h * HD;
    size_t ro1 = ((size_t)(b * S_LEN) + q1) * DM + h * HD;
#pragma unroll
    for (int ni = 0; ni < 16; ni++) {
        int c = ni * 8 + 2 * t;
        *(float2*)(Out + ro0 + c) =
            make_float2(f2tf32f(o[ni][0] * inv0), f2tf32f(o[ni][1] * inv0));
        *(float2*)(Out + ro1 + c) =
            make_float2(f2tf32f(o[ni][2] * inv1), f2tf32f(o[ni][3] * inv1));
    }
}

// ---------------- launch ----------------
extern "C" void kernel_launch(void* const* d_in, const int* in_sizes, int n_in,
                              void* d_out, int out_size) {
    const float* x  = (const float*)d_in[0];
    const float* rc = (const float*)d_in[1];
    const float* rs = (const float*)d_in[2];
    const float* Wq = (const float*)d_in[3];
    const float* Wk = (const float*)d_in[4];
    const float* Wv = (const float*)d_in[5];
    const float* Wo = (const float*)d_in[6];
    float* out = (float*)d_out;

    float *qlin, *klin, *vlin, *q, *k, *v, *att;
    float *xr, *wq, *wk, *wv, *wo;
    cudaGetSymbolAddress((void**)&qlin, g_qlin);
    cudaGetSymbolAddress((void**)&klin, g_klin);
    cudaGetSymbolAddress((void**)&vlin, g_vlin);
    cudaGetSymbolAddress((void**)&q,    g_q);
    cudaGetSymbolAddress((void**)&k,    g_k);
    cudaGetSymbolAddress((void**)&v,    g_v);
    cudaGetSymbolAddress((void**)&att,  g_att);
    cudaGetSymbolAddress((void**)&xr,   g_xr);
    cudaGetSymbolAddress((void**)&wq,   g_wq);
    cudaGetSymbolAddress((void**)&wk,   g_wk);
    cudaGetSymbolAddress((void**)&wv,   g_wv);
    cudaGetSymbolAddress((void**)&wo,   g_wo);

    const int ATT_SMEM = ATT_SMEM_FLOATS * 4;
    cudaFuncSetAttribute(attn_tf32, cudaFuncAttributeMaxDynamicSharedMemorySize, ATT_SMEM);
    cudaFuncSetAttribute(qkv_gemm, cudaFuncAttributeMaxDynamicSharedMemorySize, GEMM_SMEM_BYTES);
    cudaFuncSetAttribute(out_gemm, cudaFuncAttributeMaxDynamicSharedMemorySize, GEMM_SMEM_BYTES);

    // pre-round GEMM inputs to tf32
    round_tf32<<<(4096 * 2048 / 4 + 255) / 256, 256>>>(x,  xr, 4096 * 2048 / 4);
    round_tf32<<<(2048 * 2048 / 4 + 255) / 256, 256>>>(Wq, wq, 2048 * 2048 / 4);
    round_tf32<<<(2048 * 512  / 4 + 255) / 256, 256>>>(Wk, wk, 2048 * 512 / 4);
    round_tf32<<<(2048 * 512  / 4 + 255) / 256, 256>>>(Wv, wv, 2048 * 512 / 4);
    round_tf32<<<(2048 * 2048 / 4 + 255) / 256, 256>>>(Wo, wo, 2048 * 2048 / 4);

    // merged QKV projection (TF32 tensor cores, cp.async double-buffered)
    qkv_gemm<<<dim3(24, 32), 256, GEMM_SMEM_BYTES>>>(xr, wq, wk, wv, qlin, klin, vlin);

    // rope + relayout (tf32-pre-rounded outputs feed cp.async attention)
    rope_kernel<<<(2 * NH  * S_LEN * 64) / 256, 256>>>(qlin, rc, rs, q, NH);
    rope_kernel<<<(2 * NKV * S_LEN * 64) / 256, 256>>>(klin, rc, rs, k, NKV);
    vtrans_kernel<<<(2 * NKV * S_LEN * 128) / 256, 256>>>(vlin, v);

    // attention (TF32 tensor cores, 2-stage cp.async K/V pipeline)
    attn_tf32<<<dim3(S_LEN / 128, NH, 2), 256, ATT_SMEM>>>(q, k, v, att);

    // output projection
    out_gemm<<<dim3(16, 32), 256, GEMM_SMEM_BYTES>>>(att, wo, out);
}

// round 16
// speedup vs baseline: 3.8068x; 1.0396x over previous
#include <cuda_runtime.h>
#include <cstdint>
#include <math.h>

#define S_LEN 2048
#define DM    2048
#define NH    16
#define NKV   4
#define HD    128

// ---------------- scratch (device globals; no runtime allocation) ----------------
__device__ float g_qlin[4096u * 2048u];
__device__ float g_klin[4096u * 512u];
__device__ float g_vlin[4096u * 512u];
__device__ float g_q[4096u * 2048u];
__device__ float g_k[2u * 4u * 2048u * 128u];
__device__ float g_v[2u * 4u * 2048u * 128u];
__device__ float g_att[4096u * 2048u];
// tf32-pre-rounded copies of GEMM inputs (so cp.async + mma truncation == rna rounding)
__device__ float g_xr[4096u * 2048u];
__device__ float g_wq[2048u * 2048u];
__device__ float g_wk[2048u * 512u];
__device__ float g_wv[2048u * 512u];
__device__ float g_wo[2048u * 2048u];

// ---------------- helpers ----------------
__device__ __forceinline__ uint32_t f2tf32(float x) {
    uint32_t r;
    asm("cvt.rna.tf32.f32 %0, %1;" : "=r"(r) : "f"(x));
    return r;
}
__device__ __forceinline__ float f2tf32f(float x) { return __uint_as_float(f2tf32(x)); }

__device__ __forceinline__ void mma_tf32(float c[4], uint32_t a0, uint32_t a1,
                                         uint32_t a2, uint32_t a3,
                                         uint32_t b0, uint32_t b1) {
    asm volatile(
        "mma.sync.aligned.m16n8k8.row.col.f32.tf32.tf32.f32 "
        "{%0,%1,%2,%3}, {%4,%5,%6,%7}, {%8,%9}, {%0,%1,%2,%3};\n"
        : "+f"(c[0]), "+f"(c[1]), "+f"(c[2]), "+f"(c[3])
        : "r"(a0), "r"(a1), "r"(a2), "r"(a3), "r"(b0), "r"(b1));
}

__device__ __forceinline__ void cp16(float* smem_dst, const float* gmem_src) {
    uint32_t s = (uint32_t)__cvta_generic_to_shared(smem_dst);
    asm volatile("cp.async.cg.shared.global [%0], [%1], 16;\n" :: "r"(s), "l"(gmem_src));
}

// ---------------- fused tf32 pre-round over all 5 GEMM inputs ----------------
#define R_N0 2097152              // x    (4096*2048/4)
#define R_N1 (R_N0 + 1048576)     // + Wq (2048*2048/4)
#define R_N2 (R_N1 + 262144)      // + Wk
#define R_N3 (R_N2 + 262144)      // + Wv
#define R_N4 (R_N3 + 1048576)     // + Wo
__global__ void round_all(
    const float* __restrict__ x,  const float* __restrict__ Wq,
    const float* __restrict__ Wk, const float* __restrict__ Wv,
    const float* __restrict__ Wo,
    float* __restrict__ xr, float* __restrict__ wq, float* __restrict__ wk,
    float* __restrict__ wv, float* __restrict__ wo) {
    int i = blockIdx.x * blockDim.x + threadIdx.x;
    const float4* s; float4* d; int j;
    if (i < R_N0)      { s = (const float4*)x;  d = (float4*)xr; j = i; }
    else if (i < R_N1) { s = (const float4*)Wq; d = (float4*)wq; j = i - R_N0; }
    else if (i < R_N2) { s = (const float4*)Wk; d = (float4*)wk; j = i - R_N1; }
    else if (i < R_N3) { s = (const float4*)Wv; d = (float4*)wv; j = i - R_N2; }
    else if (i < R_N4) { s = (const float4*)Wo; d = (float4*)wo; j = i - R_N3; }
    else return;
    float4 v = s[j];
    v.x = f2tf32f(v.x); v.y = f2tf32f(v.y);
    v.z = f2tf32f(v.z); v.w = f2tf32f(v.w);
    d[j] = v;
}

// ---------------- TF32 GEMM body: C[128x128 tile] = A*B, cp.async double-buffered ----
#define GS_A   (128 * 36)
#define GS_B   (32 * 136)
#define GS_ST  (GS_A + GS_B)
#define GEMM_SMEM_BYTES (2 * GS_ST * 4)      // 71680

__device__ __forceinline__ void gemm_body(int N, int K,
    const float* __restrict__ A, const float* __restrict__ B, float* __restrict__ C,
    int bx, int by, float* sm) {
    const int tid  = threadIdx.x;
    const int lane = tid & 31, wid = tid >> 5;
    const int g = lane >> 2, t = lane & 3;
    const int wm = (wid >> 2) * 64, wn = (wid & 3) * 32;

    A += (size_t)by * 128 * K;
    B += (size_t)bx * 128;
    C += (size_t)by * 128 * N + (size_t)bx * 128;

    float acc[4][4][4];
#pragma unroll
    for (int mi = 0; mi < 4; mi++)
#pragma unroll
        for (int ni = 0; ni < 4; ni++)
#pragma unroll
            for (int r = 0; r < 4; r++) acc[mi][ni][r] = 0.f;

    const int niter = K >> 5;

    {
        float* As = sm; float* Bs = sm + GS_A;
#pragma unroll
        for (int it = 0; it < 4; it++) {
            int idx = tid + it * 256;
            int r = idx >> 3, c4 = (idx & 7) << 2;
            cp16(As + r * 36 + c4, A + (size_t)r * K + c4);
        }
#pragma unroll
        for (int it = 0; it < 4; it++) {
            int idx = tid + it * 256;
            int r = idx >> 5, c4 = (idx & 31) << 2;
            cp16(Bs + r * 136 + c4, B + (size_t)r * N + c4);
        }
        asm volatile("cp.async.commit_group;\n");
    }

    for (int i = 0; i < niter; i++) {
        float* As = sm + (i & 1) * GS_ST;
        float* Bs = As + GS_A;
        if (i + 1 < niter) {
            float* An = sm + ((i + 1) & 1) * GS_ST;
            float* Bn = An + GS_A;
            int k0 = (i + 1) << 5;
#pragma unroll
            for (int it = 0; it < 4; it++) {
                int idx = tid + it * 256;
                int r = idx >> 3, c4 = (idx & 7) << 2;
                cp16(An + r * 36 + c4, A + (size_t)r * K + k0 + c4);
            }
#pragma unroll
            for (int it = 0; it < 4; it++) {
                int idx = tid + it * 256;
                int r = idx >> 5, c4 = (idx & 31) << 2;
                cp16(Bn + r * 136 + c4, B + (size_t)(k0 + r) * N + c4);
            }
            asm volatile("cp.async.commit_group;\n");
            asm volatile("cp.async.wait_group 1;\n");
        } else {
            asm volatile("cp.async.wait_group 0;\n");
        }
        __syncthreads();

#pragma unroll
        for (int kk = 0; kk < 32; kk += 8) {
            uint32_t af[4][4], bf[4][2];
#pragma unroll
            for (int mi = 0; mi < 4; mi++) {
                const float* ar = As + (wm + mi * 16 + g) * 36 + kk + t;
                af[mi][0] = __float_as_uint(ar[0]);
                af[mi][1] = __float_as_uint(ar[8 * 36]);
                af[mi][2] = __float_as_uint(ar[4]);
                af[mi][3] = __float_as_uint(ar[8 * 36 + 4]);
            }
#pragma unroll
            for (int ni = 0; ni < 4; ni++) {
                const float* br = Bs + (kk + t) * 136 + wn + ni * 8 + g;
                bf[ni][0] = __float_as_uint(br[0]);
                bf[ni][1] = __float_as_uint(br[4 * 136]);
            }
#pragma unroll
            for (int mi = 0; mi < 4; mi++)
#pragma unroll
                for (int ni = 0; ni < 4; ni++)
                    mma_tf32(acc[mi][ni], af[mi][0], af[mi][1], af[mi][2], af[mi][3],
                             bf[ni][0], bf[ni][1]);
        }
        __syncthreads();
    }

#pragma unroll
    for (int mi = 0; mi < 4; mi++) {
#pragma unroll
        for (int ni = 0; ni < 4; ni++) {
            int row = wm + mi * 16 + g;
            int col = wn + ni * 8 + 2 * t;
            *(float2*)(C + (size_t)row * N + col) =
                make_float2(acc[mi][ni][0], acc[mi][ni][1]);
            *(float2*)(C + (size_t)(row + 8) * N + col) =
                make_float2(acc[mi][ni][2], acc[mi][ni][3]);
        }
    }
}

// Merged QKV projection: grid.x = 24 (16 Wq tiles + 4 Wk + 4 Wv), grid.y = 32.
__global__ __launch_bounds__(256, 2) void qkv_gemm(
    const float* __restrict__ x,
    const float* __restrict__ Wq, const float* __restrict__ Wk, const float* __restrict__ Wv,
    float* __restrict__ qlin, float* __restrict__ klin, float* __restrict__ vlin) {
    extern __shared__ float sm[];
    int bx = blockIdx.x;
    const float* B; float* C; int N, nbx;
    if (bx < 16)      { B = Wq; C = qlin; N = 2048; nbx = bx; }
    else if (bx < 20) { B = Wk; C = klin; N = 512;  nbx = bx - 16; }
    else              { B = Wv; C = vlin; N = 512;  nbx = bx - 20; }
    gemm_body(N, 2048, x, B, C, nbx, blockIdx.y, sm);
}

__global__ __launch_bounds__(256, 2) void out_gemm(
    const float* __restrict__ A, const float* __restrict__ B, float* __restrict__ C) {
    extern __shared__ float sm[];
    gemm_body(2048, 2048, A, B, C, blockIdx.x, blockIdx.y, sm);
}

// ---------------- RoPE + relayout; outputs tf32-pre-rounded for cp.async attention ----
__global__ void rope_kernel(const float* __restrict__ lin, const float* __restrict__ cosv,
                            const float* __restrict__ sinv, float* __restrict__ out, int nh) {
    int idx = blockIdx.x * blockDim.x + threadIdx.x;
    int i = idx & 63;
    int s = (idx >> 6) & (S_LEN - 1);
    int bh = idx >> 17;
    int h = bh % nh;
    int b = bh / nh;

    float c  = cosv[s * 64 + i];
    float sn = sinv[s * 64 + i];
    const float* src = lin + ((size_t)(b * S_LEN + s)) * (nh * HD) + h * HD + 2 * i;
    float e = src[0], o = src[1];
    float* dst = out + (((size_t)bh) * S_LEN + s) * HD + 2 * i;
    dst[0] = f2tf32f(e * c - o * sn);
    dst[1] = f2tf32f(e * sn + o * c);
}

// ---------------- V relayout [B,S,kv*HD] -> [B,kv,S,HD], tf32-pre-rounded ----------------
__global__ void vtrans_kernel(const float* __restrict__ lin, float* __restrict__ out) {
    int idx = blockIdx.x * blockDim.x + threadIdx.x;
    int d = idx & 127;
    int s = (idx >> 7) & (S_LEN - 1);
    int kvb = idx >> 18;
    int kv = kvb & 3;
    int b = kvb >> 2;
    out[idx] = f2tf32f(lin[((size_t)(b * S_LEN + s)) * (NKV * HD) + kv * HD + d]);
}

// ---------------- TF32 tensor-core flash attention (causal, GQA) ----------------
// BQ=128, BK=64, 2-stage cp.async K/V pipeline; P kept in registers via
// shfl-transpose of the S accumulator fragments (no P smem buffer).
#define AQ_STR 132
#define VS_STR 136
#define ATT_SMEM_FLOATS (128*AQ_STR + 2*64*AQ_STR + 2*64*VS_STR)

__global__ __launch_bounds__(256) void attn_tf32(const float* __restrict__ Q,
    const float* __restrict__ K, const float* __restrict__ V, float* __restrict__ Out) {
    extern __shared__ float smf[];
    float* Qs = smf;                         // [128][132]
    float* Ks = Qs + 128 * AQ_STR;           // 2 stages [64][132]
    float* Vs = Ks + 2 * 64 * AQ_STR;        // 2 stages [64][136]

    const int qt = (int)gridDim.x - 1 - (int)blockIdx.x;  // heavy tiles first
    const int h  = blockIdx.y;
    const int b  = blockIdx.z;
    const int kvh = h >> 2;
    const int tid = threadIdx.x;
    const int lane = tid & 31, w = tid >> 5;
    const int g = lane >> 2, t = lane & 3;
    const float scale = 0.08838834764831845f;

    // shfl-transpose source lanes (constant per thread)
    const int src0 = (lane & ~3) | (t >> 1);   // 4g + t/2
    const int src2 = src0 + 2;                 // 4g + t/2 + 2
    const bool todd = (t & 1);

    const float* Qg = Q + (((size_t)(b * NH + h)) * S_LEN + qt * 128) * HD;
    const float* Kg = K + ((size_t)(b * NKV + kvh)) * S_LEN * HD;
    const float* Vg = V + ((size_t)(b * NKV + kvh)) * S_LEN * HD;

    // prologue: Q tile + K/V stage 0, one cp.async group
#pragma unroll
    for (int it = 0; it < 16; it++) {
        int i4 = tid + it * 256;
        int r = i4 >> 5, c = (i4 & 31) << 2;
        cp16(Qs + r * AQ_STR + c, Qg + (size_t)r * HD + c);
    }
#pragma unroll
    for (int it = 0; it < 8; it++) {
        int i4 = tid + it * 256;
        int r = i4 >> 5, c = (i4 & 31) << 2;
        cp16(Ks + r * AQ_STR + c, Kg + (size_t)r * HD + c);
        cp16(Vs + r * VS_STR + c, Vg + (size_t)r * HD + c);
    }
    asm volatile("cp.async.commit_group;\n");

    float o[16][4];
#pragma unroll
    for (int ni = 0; ni < 16; ni++)
#pragma unroll
        for (int r = 0; r < 4; r++) o[ni][r] = 0.f;

    float m0 = -1e30f, m1 = -1e30f, l0 = 0.f, l1 = 0.f;
    const int q0 = qt * 128 + w * 16 + g;
    const int q1 = q0 + 8;

    const int nkt = 2 * qt + 2;
    for (int kt = 0; kt < nkt; kt++) {
        float* Kst = Ks + (kt & 1) * 64 * AQ_STR;
        float* Vst = Vs + (kt & 1) * 64 * VS_STR;
        if (kt + 1 < nkt) {
            float* Kn = Ks + ((kt + 1) & 1) * 64 * AQ_STR;
            float* Vn = Vs + ((kt + 1) & 1) * 64 * VS_STR;
            const float* Kgn = Kg + (size_t)(kt + 1) * 64 * HD;
            const float* Vgn = Vg + (size_t)(kt + 1) * 64 * HD;
#pragma unroll
            for (int it = 0; it < 8; it++) {
                int i4 = tid + it * 256;
                int r = i4 >> 5, c = (i4 & 31) << 2;
                cp16(Kn + r * AQ_STR + c, Kgn + (size_t)r * HD + c);
                cp16(Vn + r * VS_STR + c, Vgn + (size_t)r * HD + c);
            }
            asm volatile("cp.async.commit_group;\n");
            asm volatile("cp.async.wait_group 1;\n");
        } else {
            asm volatile("cp.async.wait_group 0;\n");
        }
        __syncthreads();

        // ---- S = Q K^T : warp computes 16x64 ----
        float sfr[8][4];
#pragma unroll
        for (int ni = 0; ni < 8; ni++)
#pragma unroll
            for (int r = 0; r < 4; r++) sfr[ni][r] = 0.f;

#pragma unroll
        for (int kk = 0; kk < 16; kk++) {
            const float* qr = Qs + (w * 16 + g) * AQ_STR + kk * 8 + t;
            uint32_t a0 = __float_as_uint(qr[0]);
            uint32_t a1 = __float_as_uint(qr[8 * AQ_STR]);
            uint32_t a2 = __float_as_uint(qr[4]);
            uint32_t a3 = __float_as_uint(qr[8 * AQ_STR + 4]);
#pragma unroll
            for (int ni = 0; ni < 8; ni++) {
                const float* kr = Kst + (ni * 8 + g) * AQ_STR + kk * 8 + t;
                mma_tf32(sfr[ni], a0, a1, a2, a3,
                         __float_as_uint(kr[0]), __float_as_uint(kr[4]));
            }
        }

        // ---- mask + scale (only tiles straddling the diagonal) ----
        const bool nm = (kt >= 2 * qt);
#pragma unroll
        for (int ni = 0; ni < 8; ni++) {
            int kb = kt * 64 + ni * 8 + 2 * t;
            float s0 = sfr[ni][0] * scale, s1 = sfr[ni][1] * scale;
            float s2 = sfr[ni][2] * scale, s3 = sfr[ni][3] * scale;
            if (nm) {
                if (kb     > q0) s0 = -1e30f;
                if (kb + 1 > q0) s1 = -1e30f;
                if (kb     > q1) s2 = -1e30f;
                if (kb + 1 > q1) s3 = -1e30f;
            }
            sfr[ni][0] = s0; sfr[ni][1] = s1; sfr[ni][2] = s2; sfr[ni][3] = s3;
        }

        // ---- online softmax (register-resident; quad shfl reduce) ----
        float mn0 = -1e30f, mn1 = -1e30f;
#pragma unroll
        for (int ni = 0; ni < 8; ni++) {
            mn0 = fmaxf(mn0, fmaxf(sfr[ni][0], sfr[ni][1]));
            mn1 = fmaxf(mn1, fmaxf(sfr[ni][2], sfr[ni][3]));
        }
        mn0 = fmaxf(mn0, __shfl_xor_sync(0xffffffffu, mn0, 1));
        mn0 = fmaxf(mn0, __shfl_xor_sync(0xffffffffu, mn0, 2));
        mn1 = fmaxf(mn1, __shfl_xor_sync(0xffffffffu, mn1, 1));
        mn1 = fmaxf(mn1, __shfl_xor_sync(0xffffffffu, mn1, 2));

        float nmx0 = fmaxf(m0, mn0), nmx1 = fmaxf(m1, mn1);
        float al0 = __expf(m0 - nmx0), al1 = __expf(m1 - nmx1);
        m0 = nmx0; m1 = nmx1;

        float sum0 = 0.f, sum1 = 0.f;
#pragma unroll
        for (int ni = 0; ni < 8; ni++) {
            float p0 = __expf(sfr[ni][0] - m0);
            float p1 = __expf(sfr[ni][1] - m0);
            float p2 = __expf(sfr[ni][2] - m1);
            float p3 = __expf(sfr[ni][3] - m1);
            sum0 += p0 + p1; sum1 += p2 + p3;
            sfr[ni][0] = f2tf32f(p0);
            sfr[ni][1] = f2tf32f(p1);
            sfr[ni][2] = f2tf32f(p2);
            sfr[ni][3] = f2tf32f(p3);
        }
        sum0 += __shfl_xor_sync(0xffffffffu, sum0, 1);
        sum0 += __shfl_xor_sync(0xffffffffu, sum0, 2);
        sum1 += __shfl_xor_sync(0xffffffffu, sum1, 1);
        sum1 += __shfl_xor_sync(0xffffffffu, sum1, 2);
        l0 = l0 * al0 + sum0;
        l1 = l1 * al1 + sum1;

#pragma unroll
        for (int ni = 0; ni < 16; ni++) {
            o[ni][0] *= al0; o[ni][1] *= al0;
            o[ni][2] *= al1; o[ni][3] *= al1;
        }

        // ---- O += P V : shfl-transpose P frags, then mma ----
#pragma unroll
        for (int kk = 0; kk < 8; kk++) {
            // a0 = P[g][kk*8+t], a1 = P[g+8][kk*8+t],
            // a2 = P[g][kk*8+t+4], a3 = P[g+8][kk*8+t+4]
            float c0s0 = __shfl_sync(0xffffffffu, sfr[kk][0], src0);
            float c1s0 = __shfl_sync(0xffffffffu, sfr[kk][1], src0);
            float c2s0 = __shfl_sync(0xffffffffu, sfr[kk][2], src0);
            float c3s0 = __shfl_sync(0xffffffffu, sfr[kk][3], src0);
            float c0s2 = __shfl_sync(0xffffffffu, sfr[kk][0], src2);
            float c1s2 = __shfl_sync(0xffffffffu, sfr[kk][1], src2);
            float c2s2 = __shfl_sync(0xffffffffu, sfr[kk][2], src2);
            float c3s2 = __shfl_sync(0xffffffffu, sfr[kk][3], src2);
            uint32_t a0 = __float_as_uint(todd ? c1s0 : c0s0);
            uint32_t a1 = __float_as_uint(todd ? c3s0 : c2s0);
            uint32_t a2 = __float_as_uint(todd ? c1s2 : c0s2);
            uint32_t a3 = __float_as_uint(todd ? c3s2 : c2s2);
#pragma unroll
            for (int ni = 0; ni < 16; ni++) {
                const float* vr = Vst + (kk * 8 + t) * VS_STR + ni * 8 + g;
                mma_tf32(o[ni], a0, a1, a2, a3,
                         __float_as_uint(vr[0]), __float_as_uint(vr[4 * VS_STR]));
            }
        }
        __syncthreads();   // stage free before next iteration's prefetch
    }

    // epilogue: rna-round outputs so the Wo GEMM's truncation is lossless
    float inv0 = 1.f / l0, inv1 = 1.f / l1;
    size_t ro0 = ((size_t)(b * S_LEN) + q0) * DM + h * HD;
    size_t ro1 = ((size_t)(b * S_LEN) + q1) * DM + h * HD;
#pragma unroll
    for (int ni = 0; ni < 16; ni++) {
        int c = ni * 8 + 2 * t;
        *(float2*)(Out + ro0 + c) =
            make_float2(f2tf32f(o[ni][0] * inv0), f2tf32f(o[ni][1] * inv0));
        *(float2*)(Out + ro1 + c) =
            make_float2(f2tf32f(o[ni][2] * inv1), f2tf32f(o[ni][3] * inv1));
    }
}

// ---------------- launch ----------------
extern "C" void kernel_launch(void* const* d_in, const int* in_sizes, int n_in,
                              void* d_out, int out_size) {
    const float* x  = (const float*)d_in[0];
    const float* rc = (const float*)d_in[1];
    const float* rs = (const float*)d_in[2];
    const float* Wq = (const float*)d_in[3];
    const float* Wk = (const float*)d_in[4];
    const float* Wv = (const float*)d_in[5];
    const float* Wo = (const float*)d_in[6];
    float* out = (float*)d_out;

    float *qlin, *klin, *vlin, *q, *k, *v, *att;
    float *xr, *wq, *wk, *wv, *wo;
    cudaGetSymbolAddress((void**)&qlin, g_qlin);
    cudaGetSymbolAddress((void**)&klin, g_klin);
    cudaGetSymbolAddress((void**)&vlin, g_vlin);
    cudaGetSymbolAddress((void**)&q,    g_q);
    cudaGetSymbolAddress((void**)&k,    g_k);
    cudaGetSymbolAddress((void**)&v,    g_v);
    cudaGetSymbolAddress((void**)&att,  g_att);
    cudaGetSymbolAddress((void**)&xr,   g_xr);
    cudaGetSymbolAddress((void**)&wq,   g_wq);
    cudaGetSymbolAddress((void**)&wk,   g_wk);
    cudaGetSymbolAddress((void**)&wv,   g_wv);
    cudaGetSymbolAddress((void**)&wo,   g_wo);

    const int ATT_SMEM = ATT_SMEM_FLOATS * 4;   // 200 KB
    cudaFuncSetAttribute(attn_tf32, cudaFuncAttributeMaxDynamicSharedMemorySize, ATT_SMEM);
    cudaFuncSetAttribute(qkv_gemm, cudaFuncAttributeMaxDynamicSharedMemorySize, GEMM_SMEM_BYTES);
    cudaFuncSetAttribute(out_gemm, cudaFuncAttributeMaxDynamicSharedMemorySize, GEMM_SMEM_BYTES);

    // fused tf32 pre-round of all GEMM inputs (one launch)
    round_all<<<(R_N4 + 255) / 256, 256>>>(x, Wq, Wk, Wv, Wo, xr, wq, wk, wv, wo);

    // merged QKV projection (TF32 tensor cores, cp.async double-buffered)
    qkv_gemm<<<dim3(24, 32), 256, GEMM_SMEM_BYTES>>>(xr, wq, wk, wv, qlin, klin, vlin);

    // rope + relayout (tf32-pre-rounded outputs feed cp.async attention)
    rope_kernel<<<(2 * NH  * S_LEN * 64) / 256, 256>>>(qlin, rc, rs, q, NH);
    rope_kernel<<<(2 * NKV * S_LEN * 64) / 256, 256>>>(klin, rc, rs, k, NKV);
    vtrans_kernel<<<(2 * NKV * S_LEN * 128) / 256, 256>>>(vlin, v);

    // attention (TF32 tensor cores, BK=64, 2-stage cp.async, shfl-transposed P)
    attn_tf32<<<dim3(S_LEN / 128, NH, 2), 256, ATT_SMEM>>>(q, k, v, att);

    // output projection
    out_gemm<<<dim3(16, 32), 256, GEMM_SMEM_BYTES>>>(att, wo, out);
}